// round 2
// baseline (speedup 1.0000x reference)
#include <cuda_runtime.h>

// Problem constants
#define B_   32
#define C_   64
#define K_   128
#define H_   64
#define OH_  62
#define LOCS 123008            // 32*62*62
#define Y_ELEMS 15745024       // 32*128*62*62

// Scratch (static device globals; no allocations allowed)
__device__ float g_wn[C_ * 9 * K_];      // normalized weights, layout [c][tap][k]
__device__ int   g_winner[LOCS];         // winner channel per (b,oh,ow), linear b*3844+oh*62+ow
__device__ int   g_index[LOCS];          // binned location ids (b<<12 | h<<6 | w)
__device__ int   g_counts[K_];
__device__ int   g_offs[K_ + 1];
__device__ int   g_cursor[K_];

// ---------------------------------------------------------------------------
// Kernel 1: weight normalization + transpose to [c][tap][k]
// grid: 128 blocks (one per k), 64 threads (one per c)
// ---------------------------------------------------------------------------
__global__ void wnorm_kernel(const float* __restrict__ w) {
    const int k = blockIdx.x;
    const int c = threadIdx.x;
    const float* wp = w + (k * C_ + c) * 9;
    float v[9];
    float ssq = 0.f;
#pragma unroll
    for (int t = 0; t < 9; t++) { v[t] = wp[t]; ssq += v[t] * v[t]; }
#pragma unroll
    for (int o = 16; o; o >>= 1) ssq += __shfl_down_sync(0xffffffffu, ssq, o);
    __shared__ float red[2];
    if ((c & 31) == 0) red[c >> 5] = ssq;
    __syncthreads();
    const float total = red[0] + red[1];
    const float inv = (total == 0.f) ? 1.f : (1.f / sqrtf(total));
#pragma unroll
    for (int t = 0; t < 9; t++) g_wn[(c * 9 + t) * K_ + k] = v[t] * inv;
}

// ---------------------------------------------------------------------------
// Kernel 2: direct conv (fp32) + fused argmax over the 128 output channels.
// grid: (31, 32)  -> block handles (b, 2 output rows), all 128 k, all 62 ow.
// block: 256 threads:  r = tid>>7 (row), kt = (tid>>3)&15 (8 k each),
//                      wt = tid&7 (8 ow each)
// smem: xs[64][4][68] (69632 B)  +  ws[8][9][128] (36864 B)  = 106496 B
// ---------------------------------------------------------------------------
#define CONV_SMEM_FLOATS (64 * 4 * 68 + 8 * 9 * 128)
#define CONV_SMEM_BYTES  (CONV_SMEM_FLOATS * 4)

__global__ __launch_bounds__(256, 1)
void conv_argmax_kernel(const float* __restrict__ x,
                        const float* __restrict__ bias,
                        float* __restrict__ y) {
    extern __shared__ float smem[];
    float* xs = smem;                 // [c][row 0..3][col 0..67]
    float* ws = smem + 64 * 4 * 68;   // [ci][tap][k]

    const int tid = threadIdx.x;
    const int b   = blockIdx.y;
    const int oh0 = blockIdx.x * 2;
    const int wt  = tid & 7;
    const int kt  = (tid >> 3) & 15;
    const int r   = tid >> 7;

    // Load x slab: rows oh0..oh0+3, all 64 channels, all 64 cols
    const float* xb = x + b * (C_ * H_ * H_);
    for (int q = tid; q < 4096; q += 256) {
        const int c = q >> 6, row = (q >> 4) & 3, cq = q & 15;
        float4 v = *(const float4*)(xb + (c * H_ + oh0 + row) * H_ + cq * 4);
        *(float4*)(xs + c * 272 + row * 68 + cq * 4) = v;
    }

    float acc[8][8];
#pragma unroll
    for (int kk = 0; kk < 8; kk++)
#pragma unroll
        for (int ww = 0; ww < 8; ww++) acc[kk][ww] = 0.f;

    for (int cc0 = 0; cc0 < C_; cc0 += 8) {
        __syncthreads();  // protect ws from prior readers (and xs fill on iter 0)
        const float4* wsrc = (const float4*)(g_wn + cc0 * (9 * K_));
        float4* wdst = (float4*)ws;
        for (int q = tid; q < 2304; q += 256) wdst[q] = wsrc[q];
        __syncthreads();

#pragma unroll
        for (int ci = 0; ci < 8; ci++) {
            const float* xc = xs + (cc0 + ci) * 272 + r * 68;
            const float* wc = ws + ci * (9 * K_);
#pragma unroll
            for (int i = 0; i < 3; i++) {
                const float* xrow = xc + i * 68 + wt * 8;
                float4 t0 = *(const float4*)(xrow);
                float4 t1 = *(const float4*)(xrow + 4);
                float2 t2 = *(const float2*)(xrow + 8);
                float xr[10] = {t0.x, t0.y, t0.z, t0.w,
                                t1.x, t1.y, t1.z, t1.w, t2.x, t2.y};
#pragma unroll
                for (int j = 0; j < 3; j++) {
                    const float* wv = wc + (i * 3 + j) * K_ + kt * 8;
                    float4 w0 = *(const float4*)(wv);
                    float4 w1 = *(const float4*)(wv + 4);
                    float wk[8] = {w0.x, w0.y, w0.z, w0.w, w1.x, w1.y, w1.z, w1.w};
#pragma unroll
                    for (int kk = 0; kk < 8; kk++)
#pragma unroll
                        for (int ww = 0; ww < 8; ww++)
                            acc[kk][ww] += wk[kk] * xr[j + ww];
                }
            }
        }
    }

    // bias
    float bv[8];
#pragma unroll
    for (int kk = 0; kk < 8; kk++) bv[kk] = bias[kt * 8 + kk];

    __syncthreads();  // smem reuse for argmax scratch
    float* av = smem;                // [2][64][16] values
    int*   ak = (int*)(smem + 2048); // [2][64][16] channel ids

#pragma unroll
    for (int ww = 0; ww < 8; ww++) {
        float best = -3.402823466e38f; int bk = 0;
#pragma unroll
        for (int kk = 0; kk < 8; kk++) {
            const float v = acc[kk][ww] + bv[kk];
            acc[kk][ww] = v;
            if (v > best) { best = v; bk = kt * 8 + kk; }
        }
        const int ow = wt * 8 + ww;
        av[(r * 64 + ow) * 16 + kt] = best;
        ak[(r * 64 + ow) * 16 + kt] = bk;
    }
    __syncthreads();

    if (tid < 128) {
        const int rr = tid >> 6, ow = tid & 63;
        float best = -3.402823466e38f; int bk = 0;
#pragma unroll
        for (int q = 0; q < 16; q++) {  // ascending k => strict '>' keeps lowest k on ties
            const float v = av[(rr * 64 + ow) * 16 + q];
            if (v > best) { best = v; bk = ak[(rr * 64 + ow) * 16 + q]; }
        }
        if (ow < OH_) g_winner[b * (OH_ * OH_) + (oh0 + rr) * OH_ + ow] = bk;
    }

    // store y
#pragma unroll
    for (int kk = 0; kk < 8; kk++) {
        const int k = kt * 8 + kk;
        float* yrow = y + ((b * K_ + k) * OH_ + (oh0 + r)) * OH_;
#pragma unroll
        for (int ww = 0; ww < 8; ww++) {
            const int ow = wt * 8 + ww;
            if (ow < OH_) yrow[ow] = acc[kk][ww];
        }
    }
}

// ---------------------------------------------------------------------------
// Kernels 3-6: binned hebb accumulation (no global atomics on the big array)
// ---------------------------------------------------------------------------
__global__ void zero_counts_kernel() { g_counts[threadIdx.x] = 0; }

__global__ void hist_kernel() {
    __shared__ int h[K_];
    const int tid = threadIdx.x;
    if (tid < K_) h[tid] = 0;
    __syncthreads();
    for (int i = blockIdx.x * blockDim.x + tid; i < LOCS; i += gridDim.x * blockDim.x)
        atomicAdd(&h[g_winner[i]], 1);
    __syncthreads();
    if (tid < K_ && h[tid]) atomicAdd(&g_counts[tid], h[tid]);
}

__global__ void scan_kernel() {
    __shared__ int s[K_];
    const int t = threadIdx.x;
    const int cnt = g_counts[t];
    s[t] = cnt;
    __syncthreads();
    for (int o = 1; o < K_; o <<= 1) {
        const int v = (t >= o) ? s[t - o] : 0;
        __syncthreads();
        s[t] += v;
        __syncthreads();
    }
    const int excl = s[t] - cnt;
    g_offs[t] = excl;
    g_cursor[t] = excl;
    if (t == K_ - 1) g_offs[K_] = s[K_ - 1];
}

__global__ void scatter_kernel() {
    const int ow = threadIdx.x;
    if (ow >= OH_) return;
    const int oh = blockIdx.x, b = blockIdx.y;
    const int k = g_winner[b * (OH_ * OH_) + oh * OH_ + ow];
    const int pos = atomicAdd(&g_cursor[k], 1);
    g_index[pos] = (b << 12) | (oh << 6) | ow;
}

// grid (64, 128): block owns (c = blockIdx.x, k = blockIdx.y) -> exclusive output
__global__ void hebb_kernel(const float* __restrict__ x, float* __restrict__ wu) {
    const int c = blockIdx.x, k = blockIdx.y;
    const int tid = threadIdx.x;
    const int start = g_offs[k], end = g_offs[k + 1];
    float a[9];
#pragma unroll
    for (int t = 0; t < 9; t++) a[t] = 0.f;

    for (int p = start + tid; p < end; p += 128) {
        const int loc = g_index[p];
        const int b = loc >> 12, h = (loc >> 6) & 63, ww = loc & 63;
        const float* xp = x + ((b * C_ + c) * H_ + h) * H_ + ww;
#pragma unroll
        for (int i = 0; i < 3; i++) {
            const float* rp = xp + i * H_;
            a[i * 3 + 0] += __ldg(rp);
            a[i * 3 + 1] += __ldg(rp + 1);
            a[i * 3 + 2] += __ldg(rp + 2);
        }
    }
#pragma unroll
    for (int t = 0; t < 9; t++)
#pragma unroll
        for (int o = 16; o; o >>= 1) a[t] += __shfl_down_sync(0xffffffffu, a[t], o);

    __shared__ float part[4][9];
    const int lane = tid & 31, wrp = tid >> 5;
    if (lane == 0) {
#pragma unroll
        for (int t = 0; t < 9; t++) part[wrp][t] = a[t];
    }
    __syncthreads();
    if (tid < 9) {
        const float s = part[0][tid] + part[1][tid] + part[2][tid] + part[3][tid];
        wu[(k * C_ + c) * 9 + tid] = s / 123008.0f;
    }
}

// ---------------------------------------------------------------------------
extern "C" void kernel_launch(void* const* d_in, const int* in_sizes, int n_in,
                              void* d_out, int out_size) {
    const float* x    = (const float*)d_in[0];
    const float* w    = (const float*)d_in[1];
    const float* bias = (const float*)d_in[2];
    float* y  = (float*)d_out;
    float* wu = y + Y_ELEMS;

    cudaFuncSetAttribute(conv_argmax_kernel,
                         cudaFuncAttributeMaxDynamicSharedMemorySize,
                         CONV_SMEM_BYTES);

    wnorm_kernel<<<K_, C_>>>(w);
    conv_argmax_kernel<<<dim3(31, 32), 256, CONV_SMEM_BYTES>>>(x, bias, y);
    zero_counts_kernel<<<1, K_>>>();
    hist_kernel<<<96, 256>>>();
    scan_kernel<<<1, K_>>>();
    scatter_kernel<<<dim3(62, 32), 64>>>();
    hebb_kernel<<<dim3(C_, K_), 128>>>(x, wu);
}

// round 3
// speedup vs baseline: 1.3000x; 1.3000x over previous
#include <cuda_runtime.h>

// Problem constants
#define B_   32
#define C_   64
#define K_   128
#define H_   64
#define OH_  62
#define LOCS 123008            // 32*62*62
#define Y_ELEMS 15745024       // 32*128*62*62

// Scratch (static device globals; no allocations allowed)
__device__ float g_wn[C_ * 9 * K_];      // normalized weights, layout [c][tap][k]
__device__ int   g_winner[LOCS];         // winner channel per (b,oh,ow)
__device__ int   g_index[LOCS];          // binned location ids (b<<12 | h<<6 | w)
__device__ int   g_counts[K_];
__device__ int   g_offs[K_ + 1];
__device__ int   g_cursor[K_];

// Packed f32x2 helpers (Blackwell FFMA2 path — only reachable via PTX)
__device__ __forceinline__ unsigned long long pack2(float lo, float hi) {
    unsigned long long r;
    asm("mov.b64 %0, {%1, %2};" : "=l"(r) : "f"(lo), "f"(hi));
    return r;
}
__device__ __forceinline__ void unpack2(unsigned long long v, float& lo, float& hi) {
    asm("mov.b64 {%0, %1}, %2;" : "=f"(lo), "=f"(hi) : "l"(v));
}
__device__ __forceinline__ void fma2(unsigned long long& acc,
                                     unsigned long long a,
                                     unsigned long long b) {
    asm("fma.rn.f32x2 %0, %1, %2, %0;" : "+l"(acc) : "l"(a), "l"(b));
}

// ---------------------------------------------------------------------------
// Kernel 1: weight normalization + transpose to [c][tap][k]
// ---------------------------------------------------------------------------
__global__ void wnorm_kernel(const float* __restrict__ w) {
    const int k = blockIdx.x;
    const int c = threadIdx.x;
    const float* wp = w + (k * C_ + c) * 9;
    float v[9];
    float ssq = 0.f;
#pragma unroll
    for (int t = 0; t < 9; t++) { v[t] = wp[t]; ssq += v[t] * v[t]; }
#pragma unroll
    for (int o = 16; o; o >>= 1) ssq += __shfl_down_sync(0xffffffffu, ssq, o);
    __shared__ float red[2];
    if ((c & 31) == 0) red[c >> 5] = ssq;
    __syncthreads();
    const float total = red[0] + red[1];
    const float inv = (total == 0.f) ? 1.f : (1.f / sqrtf(total));
#pragma unroll
    for (int t = 0; t < 9; t++) g_wn[(c * 9 + t) * K_ + k] = v[t] * inv;
}

// ---------------------------------------------------------------------------
// Kernel 2: direct conv (packed f32x2 / FFMA2) + fused argmax over 128 k.
// grid: (31, 32)  block 256:  r = tid>>7, kt = (tid>>3)&15, wt = tid&7
// Accumulators pair ADJACENT k (contiguous in ws) so weight pairs come
// straight out of LDS.128 with no packing; x is broadcast-packed once.
// ---------------------------------------------------------------------------
#define CONV_SMEM_FLOATS (64 * 4 * 68 + 8 * 9 * 128)
#define CONV_SMEM_BYTES  (CONV_SMEM_FLOATS * 4)

__global__ __launch_bounds__(256, 1)
void conv_argmax_kernel(const float* __restrict__ x,
                        const float* __restrict__ bias,
                        float* __restrict__ y) {
    extern __shared__ float smem[];
    float* xs = smem;                 // [c][row 0..3][col 0..67]
    float* ws = smem + 64 * 4 * 68;   // [ci][tap][k]

    const int tid = threadIdx.x;
    const int b   = blockIdx.y;
    const int oh0 = blockIdx.x * 2;
    const int wt  = tid & 7;
    const int kt  = (tid >> 3) & 15;
    const int r   = tid >> 7;

    const float* xb = x + b * (C_ * H_ * H_);
    for (int q = tid; q < 4096; q += 256) {
        const int c = q >> 6, row = (q >> 4) & 3, cq = q & 15;
        float4 v = *(const float4*)(xb + (c * H_ + oh0 + row) * H_ + cq * 4);
        *(float4*)(xs + c * 272 + row * 68 + cq * 4) = v;
    }

    // acc2[p][ww] holds (k = kt*8+2p, k+1) for spatial ww
    unsigned long long acc2[4][8];
#pragma unroll
    for (int p = 0; p < 4; p++)
#pragma unroll
        for (int ww = 0; ww < 8; ww++) acc2[p][ww] = 0ull;

    for (int cc0 = 0; cc0 < C_; cc0 += 8) {
        __syncthreads();
        const float4* wsrc = (const float4*)(g_wn + cc0 * (9 * K_));
        float4* wdst = (float4*)ws;
        for (int q = tid; q < 2304; q += 256) wdst[q] = wsrc[q];
        __syncthreads();

#pragma unroll
        for (int ci = 0; ci < 8; ci++) {
            const float* xc = xs + (cc0 + ci) * 272 + r * 68;
            const float* wc = ws + ci * (9 * K_);
#pragma unroll
            for (int i = 0; i < 3; i++) {
                const float* xrow = xc + i * 68 + wt * 8;
                float4 t0 = *(const float4*)(xrow);
                float4 t1 = *(const float4*)(xrow + 4);
                float2 t2 = *(const float2*)(xrow + 8);
                const float xr[10] = {t0.x, t0.y, t0.z, t0.w,
                                      t1.x, t1.y, t1.z, t1.w, t2.x, t2.y};
                unsigned long long xx[10];
#pragma unroll
                for (int q = 0; q < 10; q++) xx[q] = pack2(xr[q], xr[q]);
#pragma unroll
                for (int j = 0; j < 3; j++) {
                    // weight pairs read pre-packed straight from shared memory
                    const ulonglong2* wv =
                        (const ulonglong2*)(wc + (i * 3 + j) * K_ + kt * 8);
                    ulonglong2 wa = wv[0];
                    ulonglong2 wb = wv[1];
                    unsigned long long wp[4] = {wa.x, wa.y, wb.x, wb.y};
#pragma unroll
                    for (int p = 0; p < 4; p++)
#pragma unroll
                        for (int ww = 0; ww < 8; ww++)
                            fma2(acc2[p][ww], wp[p], xx[j + ww]);
                }
            }
        }
    }

    // unpack to plain fp32 accs, add bias
    float acc[8][8];
#pragma unroll
    for (int p = 0; p < 4; p++)
#pragma unroll
        for (int ww = 0; ww < 8; ww++)
            unpack2(acc2[p][ww], acc[2 * p][ww], acc[2 * p + 1][ww]);

    float bv[8];
#pragma unroll
    for (int kk = 0; kk < 8; kk++) bv[kk] = bias[kt * 8 + kk];

    __syncthreads();  // smem reuse for argmax scratch
    float* av = smem;                // [2][64][16] values
    int*   ak = (int*)(smem + 2048); // [2][64][16] channel ids

#pragma unroll
    for (int ww = 0; ww < 8; ww++) {
        float best = -3.402823466e38f; int bk = 0;
#pragma unroll
        for (int kk = 0; kk < 8; kk++) {
            const float v = acc[kk][ww] + bv[kk];
            acc[kk][ww] = v;
            if (v > best) { best = v; bk = kt * 8 + kk; }
        }
        const int ow = wt * 8 + ww;
        av[(r * 64 + ow) * 16 + kt] = best;
        ak[(r * 64 + ow) * 16 + kt] = bk;
    }
    __syncthreads();

    if (tid < 128) {
        const int rr = tid >> 6, ow = tid & 63;
        float best = -3.402823466e38f; int bk = 0;
#pragma unroll
        for (int q = 0; q < 16; q++) {  // ascending k => '>' keeps lowest k on ties
            const float v = av[(rr * 64 + ow) * 16 + q];
            if (v > best) { best = v; bk = ak[(rr * 64 + ow) * 16 + q]; }
        }
        if (ow < OH_) g_winner[b * (OH_ * OH_) + (oh0 + rr) * OH_ + ow] = bk;
    }

    // store y
#pragma unroll
    for (int kk = 0; kk < 8; kk++) {
        const int k = kt * 8 + kk;
        float* yrow = y + ((b * K_ + k) * OH_ + (oh0 + r)) * OH_;
#pragma unroll
        for (int ww = 0; ww < 8; ww++) {
            const int ow = wt * 8 + ww;
            if (ow < OH_) yrow[ow] = acc[kk][ww];
        }
    }
}

// ---------------------------------------------------------------------------
// Kernels 3-6: binned hebb accumulation (no global atomics on the big array)
// ---------------------------------------------------------------------------
__global__ void zero_counts_kernel() { g_counts[threadIdx.x] = 0; }

__global__ void hist_kernel() {
    __shared__ int h[K_];
    const int tid = threadIdx.x;
    if (tid < K_) h[tid] = 0;
    __syncthreads();
    for (int i = blockIdx.x * blockDim.x + tid; i < LOCS; i += gridDim.x * blockDim.x)
        atomicAdd(&h[g_winner[i]], 1);
    __syncthreads();
    if (tid < K_ && h[tid]) atomicAdd(&g_counts[tid], h[tid]);
}

__global__ void scan_kernel() {
    __shared__ int s[K_];
    const int t = threadIdx.x;
    const int cnt = g_counts[t];
    s[t] = cnt;
    __syncthreads();
    for (int o = 1; o < K_; o <<= 1) {
        const int v = (t >= o) ? s[t - o] : 0;
        __syncthreads();
        s[t] += v;
        __syncthreads();
    }
    const int excl = s[t] - cnt;
    g_offs[t] = excl;
    g_cursor[t] = excl;
    if (t == K_ - 1) g_offs[K_] = s[K_ - 1];
}

__global__ void scatter_kernel() {
    const int ow = threadIdx.x;
    if (ow >= OH_) return;
    const int oh = blockIdx.x, b = blockIdx.y;
    const int k = g_winner[b * (OH_ * OH_) + oh * OH_ + ow];
    const int pos = atomicAdd(&g_cursor[k], 1);
    g_index[pos] = (b << 12) | (oh << 6) | ow;
}

// grid (64, 128): block owns (c, k) -> exclusive output
__global__ void hebb_kernel(const float* __restrict__ x, float* __restrict__ wu) {
    const int c = blockIdx.x, k = blockIdx.y;
    const int tid = threadIdx.x;
    const int start = g_offs[k], end = g_offs[k + 1];
    float a[9];
#pragma unroll
    for (int t = 0; t < 9; t++) a[t] = 0.f;

    for (int p = start + tid; p < end; p += 128) {
        const int loc = g_index[p];
        const int b = loc >> 12, h = (loc >> 6) & 63, ww = loc & 63;
        const float* xp = x + ((b * C_ + c) * H_ + h) * H_ + ww;
#pragma unroll
        for (int i = 0; i < 3; i++) {
            const float* rp = xp + i * H_;
            a[i * 3 + 0] += __ldg(rp);
            a[i * 3 + 1] += __ldg(rp + 1);
            a[i * 3 + 2] += __ldg(rp + 2);
        }
    }
#pragma unroll
    for (int t = 0; t < 9; t++)
#pragma unroll
        for (int o = 16; o; o >>= 1) a[t] += __shfl_down_sync(0xffffffffu, a[t], o);

    __shared__ float part[4][9];
    const int lane = tid & 31, wrp = tid >> 5;
    if (lane == 0) {
#pragma unroll
        for (int t = 0; t < 9; t++) part[wrp][t] = a[t];
    }
    __syncthreads();
    if (tid < 9) {
        const float s = part[0][tid] + part[1][tid] + part[2][tid] + part[3][tid];
        wu[(k * C_ + c) * 9 + tid] = s / 123008.0f;
    }
}

// ---------------------------------------------------------------------------
extern "C" void kernel_launch(void* const* d_in, const int* in_sizes, int n_in,
                              void* d_out, int out_size) {
    const float* x    = (const float*)d_in[0];
    const float* w    = (const float*)d_in[1];
    const float* bias = (const float*)d_in[2];
    float* y  = (float*)d_out;
    float* wu = y + Y_ELEMS;

    cudaFuncSetAttribute(conv_argmax_kernel,
                         cudaFuncAttributeMaxDynamicSharedMemorySize,
                         CONV_SMEM_BYTES);

    wnorm_kernel<<<K_, C_>>>(w);
    conv_argmax_kernel<<<dim3(31, 32), 256, CONV_SMEM_BYTES>>>(x, bias, y);
    zero_counts_kernel<<<1, K_>>>();
    hist_kernel<<<96, 256>>>();
    scan_kernel<<<1, K_>>>();
    scatter_kernel<<<dim3(62, 32), 64>>>();
    hebb_kernel<<<dim3(C_, K_), 128>>>(x, wu);
}

// round 7
// speedup vs baseline: 1.6562x; 1.2740x over previous
#include <cuda_runtime.h>
#include <cuda_bf16.h>
#include <cstdint>

// Problem constants
#define B_   32
#define C_   64
#define K_   128
#define H_   64
#define OH_  62
#define LOCS 123008            // 32*62*62
#define Y_ELEMS 15745024       // 32*128*62*62
#define WU_ELEMS (K_ * C_ * 9)
#define MAXAMB 65536

// Static device scratch (no allocations allowed)
__device__ float g_xt[B_ * H_ * H_ * C_];   // x transposed to [b][h][w][c]
__device__ float g_wkt[K_ * C_ * 9];        // normalized weights [k][c][tap] fp32
__device__ uint4 g_wa[18 * 1152];           // 18 bf16 A slices [slice][k=128][72 bf16 padded]
__device__ int   g_winner[LOCS];
__device__ int   g_index[LOCS];
__device__ int   g_counts[K_];
__device__ int   g_offs[K_ + 1];
__device__ int   g_cursor[K_];
__device__ int   g_amb_cnt;
__device__ int   g_amb[MAXAMB];

// SMEM layout for conv (bytes)
#define SM_BIAS 0
#define SM_XH   512
#define SM_XL   (512 + 36864)
#define SM_A    (512 + 2 * 36864)
#define SM_YSM  (SM_A + 18432)
#define SM_TOTAL (SM_YSM + 128 * 132 * 4)   // 160256

__device__ __forceinline__ void mma_bf16(float* d, const uint32_t* a,
                                         uint32_t b0, uint32_t b1) {
    asm volatile(
        "mma.sync.aligned.m16n8k16.row.col.f32.bf16.bf16.f32 "
        "{%0,%1,%2,%3}, {%4,%5,%6,%7}, {%8,%9}, {%0,%1,%2,%3};"
        : "+f"(d[0]), "+f"(d[1]), "+f"(d[2]), "+f"(d[3])
        : "r"(a[0]), "r"(a[1]), "r"(a[2]), "r"(a[3]), "r"(b0), "r"(b1));
}

// ---------------------------------------------------------------------------
__global__ void zero_kernel() {
    if (threadIdx.x < K_) g_counts[threadIdx.x] = 0;
    if (threadIdx.x == 0) g_amb_cnt = 0;
}
__global__ void zero_wu_kernel(float* wu) {
    const int i = blockIdx.x * 1024 + threadIdx.x;
    if (i < WU_ELEMS) wu[i] = 0.f;
}

// ---------------------------------------------------------------------------
// transpose x -> [b][h][w][c]
// ---------------------------------------------------------------------------
__global__ void transpose_kernel(const float* __restrict__ x) {
    __shared__ float tile[64][65];
    const int h = blockIdx.x, b = blockIdx.y, tid = threadIdx.x;
    for (int idx = tid; idx < 4096; idx += 256) {
        const int c = idx >> 6, w = idx & 63;
        tile[c][w] = x[((b * C_ + c) * H_ + h) * H_ + w];
    }
    __syncthreads();
    for (int idx = tid; idx < 4096; idx += 256) {
        const int w = idx >> 6, c = idx & 63;
        g_xt[((b * H_ + h) * H_ + w) * C_ + c] = tile[c][w];
    }
}

// ---------------------------------------------------------------------------
// weight normalization -> g_wkt fp32 + 18 bf16 hi/lo A slices
// slice = j*6 + i*2 + var
// ---------------------------------------------------------------------------
__global__ void wnorm_kernel(const float* __restrict__ w) {
    const int k = blockIdx.x, c = threadIdx.x;
    const float* wp = w + (k * C_ + c) * 9;
    float v[9];
    float ssq = 0.f;
#pragma unroll
    for (int t = 0; t < 9; t++) { v[t] = wp[t]; ssq += v[t] * v[t]; }
#pragma unroll
    for (int o = 16; o; o >>= 1) ssq += __shfl_down_sync(0xffffffffu, ssq, o);
    __shared__ float red[2];
    if ((c & 31) == 0) red[c >> 5] = ssq;
    __syncthreads();
    const float total = red[0] + red[1];
    const float inv = (total == 0.f) ? 1.f : (1.f / sqrtf(total));
    unsigned short* wa = (unsigned short*)g_wa;
#pragma unroll
    for (int t = 0; t < 9; t++) {
        const float wn = v[t] * inv;
        g_wkt[k * 576 + c * 9 + t] = wn;
        const int i = t / 3, j = t % 3;
        __nv_bfloat16 hb = __float2bfloat16(wn);
        __nv_bfloat16 lb = __float2bfloat16(wn - __bfloat162float(hb));
        const int s0 = j * 6 + i * 2;
        wa[(s0)     * 9216 + k * 72 + c] = *(unsigned short*)&hb;
        wa[(s0 + 1) * 9216 + k * 72 + c] = *(unsigned short*)&lb;
    }
}

// ---------------------------------------------------------------------------
// conv via mma.sync bf16 3-term split + fused argmax + ambiguity flagging
// ---------------------------------------------------------------------------
__device__ __forceinline__ void do_pass(const uint32_t* __restrict__ ab,
                                        const uint32_t* __restrict__ xs,
                                        int i, int mbase, int nb,
                                        int g, int tig, float acc[2][8][4]) {
#pragma unroll
    for (int ks = 0; ks < 4; ks++) {
        uint32_t A[2][4];
#pragma unroll
        for (int mt = 0; mt < 2; mt++) {
            const uint32_t* Ar = ab + (mbase + mt * 16 + g) * 36 + ks * 8 + tig;
            A[mt][0] = Ar[0];
            A[mt][1] = Ar[288];
            A[mt][2] = Ar[4];
            A[mt][3] = Ar[292];
        }
#pragma unroll
        for (int nt = 0; nt < 8; nt++) {
            const uint32_t* Br = xs + (i * 64 + nb + nt * 8 + g) * 36 + ks * 8 + tig;
            const uint32_t b0 = Br[0], b1 = Br[4];
            mma_bf16(acc[0][nt], A[0], b0, b1);
            mma_bf16(acc[1][nt], A[1], b0, b1);
        }
    }
}

__device__ __forceinline__ void dump_one(float* ysm, int row, int n, float v, int j) {
    const int w = n & 63;
    if (w >= j) {
        const int idx = row * 132 + n - j;
        if (j == 0) ysm[idx] = v;
        else        ysm[idx] += v;
    }
}

__global__ __launch_bounds__(256, 1)
void conv_mma_kernel(const float* __restrict__ x,
                     const float* __restrict__ bias,
                     float* __restrict__ y) {
    extern __shared__ char smem[];
    float*    biassm = (float*)(smem + SM_BIAS);
    uint32_t* xh = (uint32_t*)(smem + SM_XH);
    uint32_t* xl = (uint32_t*)(smem + SM_XL);
    uint32_t* ab = (uint32_t*)(smem + SM_A);
    float*    ysm = (float*)(smem + SM_YSM);

    const int tid = threadIdx.x;
    const int wid = tid >> 5, lane = tid & 31;
    const int g = lane >> 2, tig = lane & 3;
    const int b = blockIdx.y;
    const int r = blockIdx.x * 2;
    const int mbase = (wid & 3) * 32;
    const int nb = (wid >> 2) * 64;

    if (tid < K_) biassm[tid] = bias[tid];

    // convert x rows r..r+3 -> bf16 hi/lo tiles [n'=tid][c], stride 72
    {
        unsigned short* xhu = (unsigned short*)xh;
        unsigned short* xlu = (unsigned short*)xl;
        const int row = tid >> 6, w = tid & 63;
        const float* xp = x + ((b * C_) * H_ + (r + row)) * H_ + w;
#pragma unroll 8
        for (int c = 0; c < C_; c++) {
            const float v = xp[c * (H_ * H_)];
            __nv_bfloat16 hb = __float2bfloat16(v);
            __nv_bfloat16 lb = __float2bfloat16(v - __bfloat162float(hb));
            xhu[tid * 72 + c] = *(unsigned short*)&hb;
            xlu[tid * 72 + c] = *(unsigned short*)&lb;
        }
    }

    float acc[2][8][4];
#pragma unroll
    for (int mt = 0; mt < 2; mt++)
#pragma unroll
        for (int nt = 0; nt < 8; nt++)
#pragma unroll
            for (int q = 0; q < 4; q++) acc[mt][nt][q] = 0.f;

    uint4 pf[5];
    {
        const uint4* gs = g_wa;
#pragma unroll
        for (int q = 0; q < 5; q++) {
            const int idx = tid + 256 * q;
            if (idx < 1152) pf[q] = gs[idx];
        }
    }

    for (int s = 0; s < 18; s++) {
        __syncthreads();
        {
            uint4* d4 = (uint4*)ab;
#pragma unroll
            for (int q = 0; q < 5; q++) {
                const int idx = tid + 256 * q;
                if (idx < 1152) d4[idx] = pf[q];
            }
        }
        __syncthreads();
        if (s < 17) {
            const uint4* gs = g_wa + (size_t)(s + 1) * 1152;
#pragma unroll
            for (int q = 0; q < 5; q++) {
                const int idx = tid + 256 * q;
                if (idx < 1152) pf[q] = gs[idx];
            }
        }
        const int j = s / 6, i = (s % 6) >> 1, var = s & 1;
        do_pass(ab, xh, i, mbase, nb, g, tig, acc);
        if (var == 0)
            do_pass(ab, xl, i, mbase, nb, g, tig, acc);

        if ((s % 6) == 5) {
#pragma unroll
            for (int mt = 0; mt < 2; mt++) {
                const int row0 = mbase + mt * 16 + g;
#pragma unroll
                for (int nt = 0; nt < 8; nt++) {
                    const int n0 = nb + nt * 8 + 2 * tig;
                    dump_one(ysm, row0,     n0,     acc[mt][nt][0], j);
                    dump_one(ysm, row0,     n0 + 1, acc[mt][nt][1], j);
                    dump_one(ysm, row0 + 8, n0,     acc[mt][nt][2], j);
                    dump_one(ysm, row0 + 8, n0 + 1, acc[mt][nt][3], j);
#pragma unroll
                    for (int q = 0; q < 4; q++) acc[mt][nt][q] = 0.f;
                }
            }
        }
    }
    __syncthreads();

    if (tid < 124) {
        const int orow = (tid >= 62) ? 1 : 0;
        const int w = tid - orow * 62;
        const int n = orow * 64 + w;
        float best = -3.402823466e38f, second = -3.402823466e38f;
        int bk = 0;
        float* ybase = y + ((size_t)b * K_ * OH_ + (r + orow)) * OH_ + w;
#pragma unroll 4
        for (int k = 0; k < K_; k++) {
            const float v = ysm[k * 132 + n] + biassm[k];
            ybase[(size_t)k * (OH_ * OH_)] = v;
            if (v > best) { second = best; best = v; bk = k; }
            else if (v > second) second = v;
        }
        const int oh = r + orow;
        g_winner[b * (OH_ * OH_) + oh * OH_ + w] = bk;
        if (best - second < 1e-3f) {
            const int p = atomicAdd(&g_amb_cnt, 1);
            if (p < MAXAMB) g_amb[p] = (b << 12) | (oh << 6) | w;
        }
    }
}

// ---------------------------------------------------------------------------
// exact fp32 winner recompute for ambiguous locations.
// One warp per location, one LANE per candidate channel, and the candidate's
// sum is a SINGLE sequential FMA chain in the exact order of the round-2
// scalar kernel (c ascending, then tap row-major), which empirically matched
// the reference argmax on every location.
// ---------------------------------------------------------------------------
__global__ void fix_kernel(const float* __restrict__ y,
                           const float* __restrict__ bias) {
    int cnt = g_amb_cnt; if (cnt > MAXAMB) cnt = MAXAMB;
    const int gw = (blockIdx.x * blockDim.x + threadIdx.x) >> 5;
    const int lane = threadIdx.x & 31;
    const int nw = (gridDim.x * blockDim.x) >> 5;
    for (int e = gw; e < cnt; e += nw) {
        const int loc = g_amb[e];
        const int b = loc >> 12, oh = (loc >> 6) & 63, ow = loc & 63;
        float v[4];
#pragma unroll
        for (int q = 0; q < 4; q++)
            v[q] = y[((size_t)(b * K_ + q * 32 + lane) * OH_ + oh) * OH_ + ow];
        float m = fmaxf(fmaxf(v[0], v[1]), fmaxf(v[2], v[3]));
#pragma unroll
        for (int o = 16; o; o >>= 1) m = fmaxf(m, __shfl_xor_sync(0xffffffffu, m, o));

        float myval = -3.402823466e38f;
        int   myk   = 0x7fffffff;
        int cidx = 0;
#pragma unroll
        for (int q = 0; q < 4; q++) {
            unsigned mask = __ballot_sync(0xffffffffu, v[q] >= m - 1e-3f);
            while (mask) {
                const int src = __ffs(mask) - 1;
                mask &= mask - 1;
                const int k = q * 32 + src;
                if ((cidx & 31) == lane) {
                    // sequential fp32 sum: c ascending, tap (i,j) row-major
                    const float* wk = g_wkt + k * 576;
                    const float* xb = g_xt + ((b * H_ + oh) * H_ + ow) * C_;
                    float s = 0.f;
                    for (int c = 0; c < C_; c++) {
                        const float* wc = wk + c * 9;
#pragma unroll
                        for (int i = 0; i < 3; i++) {
#pragma unroll
                            for (int j = 0; j < 3; j++)
                                s = fmaf(wc[i * 3 + j],
                                         xb[(i * H_ + j) * C_ + c], s);
                        }
                    }
                    const float val = s + bias[k];
                    if (val > myval || (val == myval && k < myk)) {
                        myval = val; myk = k;
                    }
                }
                cidx++;
            }
        }
        // warp argmax, tie -> lowest k
#pragma unroll
        for (int o = 16; o; o >>= 1) {
            const float ov = __shfl_xor_sync(0xffffffffu, myval, o);
            const int   ok = __shfl_xor_sync(0xffffffffu, myk, o);
            if (ov > myval || (ov == myval && ok < myk)) { myval = ov; myk = ok; }
        }
        if (lane == 0) g_winner[b * (OH_ * OH_) + oh * OH_ + ow] = myk;
    }
}

// ---------------------------------------------------------------------------
// binning: hist / scan / scatter
// ---------------------------------------------------------------------------
__global__ void hist_kernel() {
    __shared__ int h[K_];
    const int tid = threadIdx.x;
    if (tid < K_) h[tid] = 0;
    __syncthreads();
    for (int i = blockIdx.x * blockDim.x + tid; i < LOCS; i += gridDim.x * blockDim.x)
        atomicAdd(&h[g_winner[i]], 1);
    __syncthreads();
    if (tid < K_ && h[tid]) atomicAdd(&g_counts[tid], h[tid]);
}

__global__ void scan_kernel() {
    __shared__ int s[K_];
    const int t = threadIdx.x;
    const int cnt = g_counts[t];
    s[t] = cnt;
    __syncthreads();
    for (int o = 1; o < K_; o <<= 1) {
        const int v = (t >= o) ? s[t - o] : 0;
        __syncthreads();
        s[t] += v;
        __syncthreads();
    }
    const int excl = s[t] - cnt;
    g_offs[t] = excl;
    g_cursor[t] = excl;
    if (t == K_ - 1) g_offs[K_] = s[K_ - 1];
}

__global__ void scatter_kernel() {
    const int ow = threadIdx.x;
    if (ow >= OH_) return;
    const int oh = blockIdx.x, b = blockIdx.y;
    const int k = g_winner[b * (OH_ * OH_) + oh * OH_ + ow];
    const int pos = atomicAdd(&g_cursor[k], 1);
    g_index[pos] = (b << 12) | (oh << 6) | ow;
}

// ---------------------------------------------------------------------------
// hebb: NHWC gather, thread owns (tap, c-pair). grid (128 k, 4 chunks), 288 thr
// ---------------------------------------------------------------------------
__global__ void hebb_kernel(float* __restrict__ wu) {
    const int k = blockIdx.x, chunk = blockIdx.y;
    const int wid = threadIdx.x >> 5, lane = threadIdx.x & 31;
    const int i = wid / 3, j = wid % 3;
    const int start = g_offs[k], end = g_offs[k + 1];
    const int len = end - start;
    const int cs = start + (len * chunk) / 4;
    const int ce = start + (len * (chunk + 1)) / 4;
    float ax = 0.f, ay = 0.f;
    int p = cs;
    for (; p + 1 < ce; p += 2) {
        const int l0 = g_index[p], l1 = g_index[p + 1];
        const float2 v0 = *(const float2*)(g_xt +
            ((((l0 >> 12) * H_ + ((l0 >> 6) & 63) + i) * H_) + (l0 & 63) + j) * C_ + 2 * lane);
        const float2 v1 = *(const float2*)(g_xt +
            ((((l1 >> 12) * H_ + ((l1 >> 6) & 63) + i) * H_) + (l1 & 63) + j) * C_ + 2 * lane);
        ax += v0.x + v1.x; ay += v0.y + v1.y;
    }
    if (p < ce) {
        const int l0 = g_index[p];
        const float2 v0 = *(const float2*)(g_xt +
            ((((l0 >> 12) * H_ + ((l0 >> 6) & 63) + i) * H_) + (l0 & 63) + j) * C_ + 2 * lane);
        ax += v0.x; ay += v0.y;
    }
    const float sc = 1.f / 123008.f;
    atomicAdd(&wu[k * 576 + (2 * lane) * 9 + i * 3 + j], ax * sc);
    atomicAdd(&wu[k * 576 + (2 * lane + 1) * 9 + i * 3 + j], ay * sc);
}

// ---------------------------------------------------------------------------
extern "C" void kernel_launch(void* const* d_in, const int* in_sizes, int n_in,
                              void* d_out, int out_size) {
    const float* x    = (const float*)d_in[0];
    const float* w    = (const float*)d_in[1];
    const float* bias = (const float*)d_in[2];
    float* y  = (float*)d_out;
    float* wu = y + Y_ELEMS;

    cudaFuncSetAttribute(conv_mma_kernel,
                         cudaFuncAttributeMaxDynamicSharedMemorySize, SM_TOTAL);

    zero_kernel<<<1, 128>>>();
    zero_wu_kernel<<<72, 1024>>>(wu);
    transpose_kernel<<<dim3(64, 32), 256>>>(x);
    wnorm_kernel<<<K_, C_>>>(w);
    conv_mma_kernel<<<dim3(31, 32), 256, SM_TOTAL>>>(x, bias, y);
    fix_kernel<<<256, 128>>>(y, bias);
    hist_kernel<<<96, 256>>>();
    scan_kernel<<<1, K_>>>();
    scatter_kernel<<<dim3(62, 32), 64>>>();
    hebb_kernel<<<dim3(K_, 4), 288>>>(wu);
}

// round 10
// speedup vs baseline: 1.7534x; 1.0587x over previous
#include <cuda_runtime.h>
#include <cuda_bf16.h>
#include <cstdint>

// Problem constants
#define B_   32
#define C_   64
#define K_   128
#define H_   64
#define OH_  62
#define LOCS 123008            // 32*62*62
#define Y_ELEMS 15745024       // 32*128*62*62
#define WU_ELEMS (K_ * C_ * 9)
#define MAXAMB 65536

// Static device scratch (no allocations allowed)
__device__ float g_xt[B_ * H_ * H_ * C_];   // x transposed to [b][h][w][c]
__device__ float g_wkt[K_ * C_ * 9];        // normalized weights [k][c][tap] fp32
__device__ uint4 g_wa[18 * 1152];           // 18 bf16 A slices [slice][k=128][72 bf16 padded]
__device__ int   g_winner[LOCS];
__device__ int   g_index[LOCS];
__device__ int   g_counts[K_];
__device__ int   g_offs[K_ + 1];
__device__ int   g_cursor[K_];
__device__ int   g_amb_cnt;
__device__ int   g_amb[MAXAMB];

// SMEM layout for conv (bytes)
#define SM_BIAS 0
#define SM_XH   512
#define SM_XL   (512 + 36864)
#define SM_A    (512 + 2 * 36864)
#define SM_YSM  (SM_A + 18432)
#define SM_TOTAL (SM_YSM + 128 * 132 * 4)   // 160256

__device__ __forceinline__ void mma_bf16(float* d, const uint32_t* a,
                                         uint32_t b0, uint32_t b1) {
    asm volatile(
        "mma.sync.aligned.m16n8k16.row.col.f32.bf16.bf16.f32 "
        "{%0,%1,%2,%3}, {%4,%5,%6,%7}, {%8,%9}, {%0,%1,%2,%3};"
        : "+f"(d[0]), "+f"(d[1]), "+f"(d[2]), "+f"(d[3])
        : "r"(a[0]), "r"(a[1]), "r"(a[2]), "r"(a[3]), "r"(b0), "r"(b1));
}
__device__ __forceinline__ void ldsm_x4(uint32_t* r, uint32_t addr) {
    asm volatile("ldmatrix.sync.aligned.m8n8.x4.shared.b16 {%0,%1,%2,%3}, [%4];"
        : "=r"(r[0]), "=r"(r[1]), "=r"(r[2]), "=r"(r[3]) : "r"(addr));
}
__device__ __forceinline__ uint32_t smem_u32(const void* p) {
    return (uint32_t)__cvta_generic_to_shared(p);
}

// ---------------------------------------------------------------------------
__global__ void zero_kernel() {
    if (threadIdx.x < K_) g_counts[threadIdx.x] = 0;
    if (threadIdx.x == 0) g_amb_cnt = 0;
}
__global__ void zero_wu_kernel(float* wu) {
    const int i = blockIdx.x * 1024 + threadIdx.x;
    if (i < WU_ELEMS) wu[i] = 0.f;
}

// ---------------------------------------------------------------------------
// transpose x -> [b][h][w][c]
// ---------------------------------------------------------------------------
__global__ void transpose_kernel(const float* __restrict__ x) {
    __shared__ float tile[64][65];
    const int h = blockIdx.x, b = blockIdx.y, tid = threadIdx.x;
    for (int idx = tid; idx < 4096; idx += 256) {
        const int c = idx >> 6, w = idx & 63;
        tile[c][w] = x[((b * C_ + c) * H_ + h) * H_ + w];
    }
    __syncthreads();
    for (int idx = tid; idx < 4096; idx += 256) {
        const int w = idx >> 6, c = idx & 63;
        g_xt[((b * H_ + h) * H_ + w) * C_ + c] = tile[c][w];
    }
}

// ---------------------------------------------------------------------------
// weight normalization -> g_wkt fp32 + 18 bf16 hi/lo A slices
// slice = j*6 + i*2 + var
// ---------------------------------------------------------------------------
__global__ void wnorm_kernel(const float* __restrict__ w) {
    const int k = blockIdx.x, c = threadIdx.x;
    const float* wp = w + (k * C_ + c) * 9;
    float v[9];
    float ssq = 0.f;
#pragma unroll
    for (int t = 0; t < 9; t++) { v[t] = wp[t]; ssq += v[t] * v[t]; }
#pragma unroll
    for (int o = 16; o; o >>= 1) ssq += __shfl_down_sync(0xffffffffu, ssq, o);
    __shared__ float red[2];
    if ((c & 31) == 0) red[c >> 5] = ssq;
    __syncthreads();
    const float total = red[0] + red[1];
    const float inv = (total == 0.f) ? 1.f : (1.f / sqrtf(total));
    unsigned short* wa = (unsigned short*)g_wa;
#pragma unroll
    for (int t = 0; t < 9; t++) {
        const float wn = v[t] * inv;
        g_wkt[k * 576 + c * 9 + t] = wn;
        const int i = t / 3, j = t % 3;
        __nv_bfloat16 hb = __float2bfloat16(wn);
        __nv_bfloat16 lb = __float2bfloat16(wn - __bfloat162float(hb));
        const int s0 = j * 6 + i * 2;
        wa[(s0)     * 9216 + k * 72 + c] = *(unsigned short*)&hb;
        wa[(s0 + 1) * 9216 + k * 72 + c] = *(unsigned short*)&lb;
    }
}

// ---------------------------------------------------------------------------
// conv via mma.sync bf16 3-term split, ldmatrix fragment loads
// ---------------------------------------------------------------------------
__device__ __forceinline__ void do_pass_lm(uint32_t abase, uint32_t xbase,
                                           int A_lane_off, int B_lane_off,
                                           int i, float acc[2][8][4]) {
#pragma unroll
    for (int kh = 0; kh < 2; kh++) {
        uint32_t Breg[8][4];
#pragma unroll
        for (int nt = 0; nt < 8; nt++)
            ldsm_x4(Breg[nt], xbase + B_lane_off + (i * 64 + nt * 8) * 144 + kh * 64);
        uint32_t Areg[2][2][4];
#pragma unroll
        for (int mt = 0; mt < 2; mt++)
#pragma unroll
            for (int kl = 0; kl < 2; kl++)
                ldsm_x4(Areg[mt][kl], abase + A_lane_off + mt * 2304 + (kh * 2 + kl) * 32);
#pragma unroll
        for (int kl = 0; kl < 2; kl++)
#pragma unroll
            for (int nt = 0; nt < 8; nt++) {
                mma_bf16(acc[0][nt], Areg[0][kl], Breg[nt][kl * 2], Breg[nt][kl * 2 + 1]);
                mma_bf16(acc[1][nt], Areg[1][kl], Breg[nt][kl * 2], Breg[nt][kl * 2 + 1]);
            }
    }
}

__device__ __forceinline__ void dump_one(float* ysm, int row, int n, float v, int j) {
    const int w = n & 63;
    if (w >= j) {
        const int idx = row * 132 + n - j;
        if (j == 0) ysm[idx] = v;
        else        ysm[idx] += v;
    }
}

__global__ __launch_bounds__(256, 1)
void conv_mma_kernel(const float* __restrict__ bias,
                     float* __restrict__ y) {
    extern __shared__ char smem[];
    float*    biassm = (float*)(smem + SM_BIAS);
    float*    ysm = (float*)(smem + SM_YSM);

    const int tid = threadIdx.x;
    const int wid = tid >> 5, lane = tid & 31;
    const int g = lane >> 2, tig = lane & 3;
    const int lm = lane >> 3, lr = lane & 7;   // ldmatrix: matrix id, row in matrix
    const int b = blockIdx.y;
    const int r = blockIdx.x * 2;
    const int mbase = (wid & 3) * 32;
    const int nb = (wid >> 2) * 64;

    const uint32_t sbase = smem_u32(smem);
    const uint32_t abase = sbase + SM_A;
    const uint32_t xh_base = sbase + SM_XH;
    const uint32_t xl_base = sbase + SM_XL;
    const int A_lane_off = (mbase + (lm & 1) * 8 + lr) * 144 + (lm >> 1) * 16;
    const int B_lane_off = (nb + lr) * 144 + lm * 16;

    if (tid < K_) biassm[tid] = bias[tid];

    // convert x rows r..r+3 (from NHWC g_xt, coalesced) -> bf16 hi/lo tiles
    {
        unsigned short* xhu = (unsigned short*)(smem + SM_XH);
        unsigned short* xlu = (unsigned short*)(smem + SM_XL);
        const int row = tid >> 6, w = tid & 63;
        const float4* xp = (const float4*)(g_xt + (((size_t)b * H_ + (r + row)) * H_ + w) * C_);
#pragma unroll
        for (int q = 0; q < 16; q++) {
            const float4 v4 = xp[q];
            const float vv[4] = {v4.x, v4.y, v4.z, v4.w};
#pragma unroll
            for (int u = 0; u < 4; u++) {
                const int c = q * 4 + u;
                __nv_bfloat16 hb = __float2bfloat16(vv[u]);
                __nv_bfloat16 lb = __float2bfloat16(vv[u] - __bfloat162float(hb));
                xhu[tid * 72 + c] = *(unsigned short*)&hb;
                xlu[tid * 72 + c] = *(unsigned short*)&lb;
            }
        }
    }

    float acc[2][8][4];
#pragma unroll
    for (int mt = 0; mt < 2; mt++)
#pragma unroll
        for (int nt = 0; nt < 8; nt++)
#pragma unroll
            for (int q = 0; q < 4; q++) acc[mt][nt][q] = 0.f;

    uint4 pf[5];
    {
        const uint4* gs = g_wa;
#pragma unroll
        for (int q = 0; q < 5; q++) {
            const int idx = tid + 256 * q;
            if (idx < 1152) pf[q] = gs[idx];
        }
    }

    for (int s = 0; s < 18; s++) {
        __syncthreads();
        {
            uint4* d4 = (uint4*)(smem + SM_A);
#pragma unroll
            for (int q = 0; q < 5; q++) {
                const int idx = tid + 256 * q;
                if (idx < 1152) d4[idx] = pf[q];
            }
        }
        __syncthreads();
        if (s < 17) {
            const uint4* gs = g_wa + (size_t)(s + 1) * 1152;
#pragma unroll
            for (int q = 0; q < 5; q++) {
                const int idx = tid + 256 * q;
                if (idx < 1152) pf[q] = gs[idx];
            }
        }
        const int j = s / 6, i = (s % 6) >> 1, var = s & 1;
        do_pass_lm(abase, xh_base, A_lane_off, B_lane_off, i, acc);
        if (var == 0)
            do_pass_lm(abase, xl_base, A_lane_off, B_lane_off, i, acc);

        if ((s % 6) == 5) {
#pragma unroll
            for (int mt = 0; mt < 2; mt++) {
                const int row0 = mbase + mt * 16 + g;
#pragma unroll
                for (int nt = 0; nt < 8; nt++) {
                    const int n0 = nb + nt * 8 + 2 * tig;
                    dump_one(ysm, row0,     n0,     acc[mt][nt][0], j);
                    dump_one(ysm, row0,     n0 + 1, acc[mt][nt][1], j);
                    dump_one(ysm, row0 + 8, n0,     acc[mt][nt][2], j);
                    dump_one(ysm, row0 + 8, n0 + 1, acc[mt][nt][3], j);
#pragma unroll
                    for (int q = 0; q < 4; q++) acc[mt][nt][q] = 0.f;
                }
            }
        }
    }
    __syncthreads();

    // argmax + ambiguity flag (values identical to y below)
    if (tid < 124) {
        const int orow = (tid >= 62) ? 1 : 0;
        const int w = tid - orow * 62;
        const int n = orow * 64 + w;
        float best = -3.402823466e38f, second = -3.402823466e38f;
        int bk = 0;
#pragma unroll 4
        for (int k = 0; k < K_; k++) {
            const float v = ysm[k * 132 + n] + biassm[k];
            if (v > best) { second = best; best = v; bk = k; }
            else if (v > second) second = v;
        }
        const int oh = r + orow;
        g_winner[b * (OH_ * OH_) + oh * OH_ + w] = bk;
        if (best - second < 1e-3f) {
            const int p = atomicAdd(&g_amb_cnt, 1);
            if (p < MAXAMB) g_amb[p] = (b << 12) | (oh << 6) | w;
        }
    }

    // coalesced y store: warp handles 32 (k,orow) rows; row = 62 contiguous floats
    {
#pragma unroll 4
        for (int rr = 0; rr < 32; rr++) {
            const int rowid = wid * 32 + rr;
            const int k = rowid >> 1, orow = rowid & 1;
            const float bk = biassm[k];
            float* ydst = y + (((size_t)b * K_ + k) * OH_ + (r + orow)) * OH_;
            const float* ysrc = ysm + k * 132 + orow * 64;
#pragma unroll
            for (int hh = 0; hh < 2; hh++) {
                const int w = hh * 32 + lane;
                if (w < OH_) ydst[w] = ysrc[w] + bk;
            }
        }
    }
}

// ---------------------------------------------------------------------------
// exact fp32 winner recompute for ambiguous locations (order matches the
// empirically-reference-matching round-2 scalar chain).
// ---------------------------------------------------------------------------
__global__ void fix_kernel(const float* __restrict__ y,
                           const float* __restrict__ bias) {
    int cnt = g_amb_cnt; if (cnt > MAXAMB) cnt = MAXAMB;
    const int gw = (blockIdx.x * blockDim.x + threadIdx.x) >> 5;
    const int lane = threadIdx.x & 31;
    const int nw = (gridDim.x * blockDim.x) >> 5;
    for (int e = gw; e < cnt; e += nw) {
        const int loc = g_amb[e];
        const int b = loc >> 12, oh = (loc >> 6) & 63, ow = loc & 63;
        float v[4];
#pragma unroll
        for (int q = 0; q < 4; q++)
            v[q] = y[((size_t)(b * K_ + q * 32 + lane) * OH_ + oh) * OH_ + ow];
        float m = fmaxf(fmaxf(v[0], v[1]), fmaxf(v[2], v[3]));
#pragma unroll
        for (int o = 16; o; o >>= 1) m = fmaxf(m, __shfl_xor_sync(0xffffffffu, m, o));

        float myval = -3.402823466e38f;
        int   myk   = 0x7fffffff;
        int cidx = 0;
#pragma unroll
        for (int q = 0; q < 4; q++) {
            unsigned mask = __ballot_sync(0xffffffffu, v[q] >= m - 1e-3f);
            while (mask) {
                const int src = __ffs(mask) - 1;
                mask &= mask - 1;
                const int k = q * 32 + src;
                if ((cidx & 31) == lane) {
                    const float* wk = g_wkt + k * 576;
                    const float* xb = g_xt + (((size_t)b * H_ + oh) * H_ + ow) * C_;
                    float s = 0.f;
                    for (int c = 0; c < C_; c++) {
                        const float* wc = wk + c * 9;
#pragma unroll
                        for (int i = 0; i < 3; i++) {
#pragma unroll
                            for (int j = 0; j < 3; j++)
                                s = fmaf(wc[i * 3 + j],
                                         xb[(i * H_ + j) * C_ + c], s);
                        }
                    }
                    const float val = s + bias[k];
                    if (val > myval || (val == myval && k < myk)) {
                        myval = val; myk = k;
                    }
                }
                cidx++;
            }
        }
#pragma unroll
        for (int o = 16; o; o >>= 1) {
            const float ov = __shfl_xor_sync(0xffffffffu, myval, o);
            const int   ok = __shfl_xor_sync(0xffffffffu, myk, o);
            if (ov > myval || (ov == myval && ok < myk)) { myval = ov; myk = ok; }
        }
        if (lane == 0) g_winner[b * (OH_ * OH_) + oh * OH_ + ow] = myk;
    }
}

// ---------------------------------------------------------------------------
// binning: hist / scan / block-aggregated scatter
// ---------------------------------------------------------------------------
__global__ void hist_kernel() {
    __shared__ int h[K_];
    const int tid = threadIdx.x;
    if (tid < K_) h[tid] = 0;
    __syncthreads();
    for (int i = blockIdx.x * blockDim.x + tid; i < LOCS; i += gridDim.x * blockDim.x)
        atomicAdd(&h[g_winner[i]], 1);
    __syncthreads();
    if (tid < K_ && h[tid]) atomicAdd(&g_counts[tid], h[tid]);
}

__global__ void scan_kernel() {
    __shared__ int s[K_];
    const int t = threadIdx.x;
    const int cnt = g_counts[t];
    s[t] = cnt;
    __syncthreads();
    for (int o = 1; o < K_; o <<= 1) {
        const int v = (t >= o) ? s[t - o] : 0;
        __syncthreads();
        s[t] += v;
        __syncthreads();
    }
    const int excl = s[t] - cnt;
    g_offs[t] = excl;
    g_cursor[t] = excl;
    if (t == K_ - 1) g_offs[K_] = s[K_ - 1];
}

// block-aggregated scatter: one global atomic per (block, k)
__global__ void scatter_kernel() {
    __shared__ int cnt[K_], base[K_], cur[K_];
    const int tid = threadIdx.x;
    const int per = (LOCS + gridDim.x - 1) / gridDim.x;
    const int s0 = blockIdx.x * per;
    int s1 = s0 + per; if (s1 > LOCS) s1 = LOCS;
    if (tid < K_) { cnt[tid] = 0; cur[tid] = 0; }
    __syncthreads();
    for (int idx = s0 + tid; idx < s1; idx += blockDim.x)
        atomicAdd(&cnt[g_winner[idx]], 1);
    __syncthreads();
    if (tid < K_)
        base[tid] = cnt[tid] ? atomicAdd(&g_cursor[tid], cnt[tid]) : 0;
    __syncthreads();
    for (int idx = s0 + tid; idx < s1; idx += blockDim.x) {
        const int k = g_winner[idx];
        const int off = atomicAdd(&cur[k], 1);
        const int b = idx / 3844, rem = idx % 3844;
        const int oh = rem / OH_, ow = rem % OH_;
        g_index[base[k] + off] = (b << 12) | (oh << 6) | ow;
    }
}

// ---------------------------------------------------------------------------
// hebb: NHWC gather, thread owns (tap, c-pair). grid (128 k, 4 chunks), 288 thr
// ---------------------------------------------------------------------------
__global__ void hebb_kernel(float* __restrict__ wu) {
    const int k = blockIdx.x, chunk = blockIdx.y;
    const int wid = threadIdx.x >> 5, lane = threadIdx.x & 31;
    const int i = wid / 3, j = wid % 3;
    const int start = g_offs[k], end = g_offs[k + 1];
    const int len = end - start;
    const int cs = start + (len * chunk) / 4;
    const int ce = start + (len * (chunk + 1)) / 4;
    float ax = 0.f, ay = 0.f;
    int p = cs;
    for (; p + 1 < ce; p += 2) {
        const int l0 = g_index[p], l1 = g_index[p + 1];
        const float2 v0 = *(const float2*)(g_xt +
            ((((l0 >> 12) * H_ + ((l0 >> 6) & 63) + i) * H_) + (l0 & 63) + j) * C_ + 2 * lane);
        const float2 v1 = *(const float2*)(g_xt +
            ((((l1 >> 12) * H_ + ((l1 >> 6) & 63) + i) * H_) + (l1 & 63) + j) * C_ + 2 * lane);
        ax += v0.x + v1.x; ay += v0.y + v1.y;
    }
    if (p < ce) {
        const int l0 = g_index[p];
        const float2 v0 = *(const float2*)(g_xt +
            ((((l0 >> 12) * H_ + ((l0 >> 6) & 63) + i) * H_) + (l0 & 63) + j) * C_ + 2 * lane);
        ax += v0.x; ay += v0.y;
    }
    const float sc = 1.f / 123008.f;
    atomicAdd(&wu[k * 576 + (2 * lane) * 9 + i * 3 + j], ax * sc);
    atomicAdd(&wu[k * 576 + (2 * lane + 1) * 9 + i * 3 + j], ay * sc);
}

// ---------------------------------------------------------------------------
extern "C" void kernel_launch(void* const* d_in, const int* in_sizes, int n_in,
                              void* d_out, int out_size) {
    const float* x    = (const float*)d_in[0];
    const float* w    = (const float*)d_in[1];
    const float* bias = (const float*)d_in[2];
    float* y  = (float*)d_out;
    float* wu = y + Y_ELEMS;

    cudaFuncSetAttribute(conv_mma_kernel,
                         cudaFuncAttributeMaxDynamicSharedMemorySize, SM_TOTAL);

    zero_kernel<<<1, 128>>>();
    zero_wu_kernel<<<72, 1024>>>(wu);
    transpose_kernel<<<dim3(64, 32), 256>>>(x);
    wnorm_kernel<<<K_, C_>>>(w);
    conv_mma_kernel<<<dim3(31, 32), 256, SM_TOTAL>>>(bias, y);
    fix_kernel<<<256, 128>>>(y, bias);
    hist_kernel<<<96, 256>>>();
    scan_kernel<<<1, K_>>>();
    scatter_kernel<<<96, 256>>>();
    hebb_kernel<<<dim3(K_, 4), 288>>>(wu);
}

// round 11
// speedup vs baseline: 1.7981x; 1.0255x over previous
#include <cuda_runtime.h>
#include <cuda_bf16.h>
#include <cstdint>

// Problem constants
#define B_   32
#define C_   64
#define K_   128
#define H_   64
#define OH_  62
#define LOCS 123008            // 32*62*62
#define Y_ELEMS 15745024       // 32*128*62*62
#define WU_ELEMS (K_ * C_ * 9)
#define MAXAMB 65536

// Static device scratch (no allocations allowed)
__device__ float g_xt[B_ * H_ * H_ * C_];   // x transposed to [b][h][w][c]
__device__ float g_wkt[K_ * C_ * 9];        // normalized weights [k][c][tap] fp32
__device__ uint4 g_wa[18 * 1152];           // 18 bf16 A slices [slice][k=128][72 bf16 padded]
__device__ int   g_winner[LOCS];
__device__ int   g_index[LOCS];
__device__ int   g_counts[K_];
__device__ int   g_offs[K_ + 1];
__device__ int   g_cursor[K_];
__device__ int   g_amb_cnt;
__device__ int   g_amb[MAXAMB];

// SMEM layout for conv (bytes) — A is double-buffered now
#define SM_BIAS 0
#define SM_XH   512
#define SM_XL   (512 + 36864)
#define SM_A    (512 + 2 * 36864)            // 2 x 18432
#define SM_YSM  (SM_A + 2 * 18432)
#define SM_TOTAL (SM_YSM + 128 * 132 * 4)    // 178688

__device__ __forceinline__ void mma_bf16(float* d, const uint32_t* a,
                                         uint32_t b0, uint32_t b1) {
    asm volatile(
        "mma.sync.aligned.m16n8k16.row.col.f32.bf16.bf16.f32 "
        "{%0,%1,%2,%3}, {%4,%5,%6,%7}, {%8,%9}, {%0,%1,%2,%3};"
        : "+f"(d[0]), "+f"(d[1]), "+f"(d[2]), "+f"(d[3])
        : "r"(a[0]), "r"(a[1]), "r"(a[2]), "r"(a[3]), "r"(b0), "r"(b1));
}
__device__ __forceinline__ void ldsm_x4(uint32_t* r, uint32_t addr) {
    asm volatile("ldmatrix.sync.aligned.m8n8.x4.shared.b16 {%0,%1,%2,%3}, [%4];"
        : "=r"(r[0]), "=r"(r[1]), "=r"(r[2]), "=r"(r[3]) : "r"(addr));
}
__device__ __forceinline__ uint32_t smem_u32(const void* p) {
    return (uint32_t)__cvta_generic_to_shared(p);
}

// ---------------------------------------------------------------------------
// merged zero kernel
// ---------------------------------------------------------------------------
__global__ void zero_kernel(float* wu) {
    const int i = blockIdx.x * 1024 + threadIdx.x;
    if (i < WU_ELEMS) wu[i] = 0.f;
    if (blockIdx.x == 0) {
        if (threadIdx.x < K_) g_counts[threadIdx.x] = 0;
        if (threadIdx.x == 0) g_amb_cnt = 0;
    }
}

// ---------------------------------------------------------------------------
// transpose x -> [b][h][w][c]
// ---------------------------------------------------------------------------
__global__ void transpose_kernel(const float* __restrict__ x) {
    __shared__ float tile[64][65];
    const int h = blockIdx.x, b = blockIdx.y, tid = threadIdx.x;
    for (int idx = tid; idx < 4096; idx += 256) {
        const int c = idx >> 6, w = idx & 63;
        tile[c][w] = x[((b * C_ + c) * H_ + h) * H_ + w];
    }
    __syncthreads();
    for (int idx = tid; idx < 4096; idx += 256) {
        const int w = idx >> 6, c = idx & 63;
        g_xt[((b * H_ + h) * H_ + w) * C_ + c] = tile[c][w];
    }
}

// ---------------------------------------------------------------------------
// weight normalization -> g_wkt fp32 + 18 bf16 hi/lo A slices
// slice = j*6 + i*2 + var
// ---------------------------------------------------------------------------
__global__ void wnorm_kernel(const float* __restrict__ w) {
    const int k = blockIdx.x, c = threadIdx.x;
    const float* wp = w + (k * C_ + c) * 9;
    float v[9];
    float ssq = 0.f;
#pragma unroll
    for (int t = 0; t < 9; t++) { v[t] = wp[t]; ssq += v[t] * v[t]; }
#pragma unroll
    for (int o = 16; o; o >>= 1) ssq += __shfl_down_sync(0xffffffffu, ssq, o);
    __shared__ float red[2];
    if ((c & 31) == 0) red[c >> 5] = ssq;
    __syncthreads();
    const float total = red[0] + red[1];
    const float inv = (total == 0.f) ? 1.f : (1.f / sqrtf(total));
    unsigned short* wa = (unsigned short*)g_wa;
#pragma unroll
    for (int t = 0; t < 9; t++) {
        const float wn = v[t] * inv;
        g_wkt[k * 576 + c * 9 + t] = wn;
        const int i = t / 3, j = t % 3;
        __nv_bfloat16 hb = __float2bfloat16(wn);
        __nv_bfloat16 lb = __float2bfloat16(wn - __bfloat162float(hb));
        const int s0 = j * 6 + i * 2;
        wa[(s0)     * 9216 + k * 72 + c] = *(unsigned short*)&hb;
        wa[(s0 + 1) * 9216 + k * 72 + c] = *(unsigned short*)&lb;
    }
}

// ---------------------------------------------------------------------------
// conv via mma.sync bf16 3-term split, ldmatrix fragment loads,
// double-buffered A staging (one sync per slice; STS/LDG overlap compute)
// ---------------------------------------------------------------------------
__device__ __forceinline__ void do_pass_lm(uint32_t abase, uint32_t xbase,
                                           int A_lane_off, int B_lane_off,
                                           int i, float acc[2][8][4]) {
#pragma unroll
    for (int kh = 0; kh < 2; kh++) {
        uint32_t Breg[8][4];
#pragma unroll
        for (int nt = 0; nt < 8; nt++)
            ldsm_x4(Breg[nt], xbase + B_lane_off + (i * 64 + nt * 8) * 144 + kh * 64);
        uint32_t Areg[2][2][4];
#pragma unroll
        for (int mt = 0; mt < 2; mt++)
#pragma unroll
            for (int kl = 0; kl < 2; kl++)
                ldsm_x4(Areg[mt][kl], abase + A_lane_off + mt * 2304 + (kh * 2 + kl) * 32);
#pragma unroll
        for (int kl = 0; kl < 2; kl++)
#pragma unroll
            for (int nt = 0; nt < 8; nt++) {
                mma_bf16(acc[0][nt], Areg[0][kl], Breg[nt][kl * 2], Breg[nt][kl * 2 + 1]);
                mma_bf16(acc[1][nt], Areg[1][kl], Breg[nt][kl * 2], Breg[nt][kl * 2 + 1]);
            }
    }
}

__device__ __forceinline__ void dump_one(float* ysm, int row, int n, float v, int j) {
    const int w = n & 63;
    if (w >= j) {
        const int idx = row * 132 + n - j;
        if (j == 0) ysm[idx] = v;
        else        ysm[idx] += v;
    }
}

__global__ __launch_bounds__(256, 1)
void conv_mma_kernel(const float* __restrict__ bias,
                     float* __restrict__ y) {
    extern __shared__ char smem[];
    float*    biassm = (float*)(smem + SM_BIAS);
    float*    ysm = (float*)(smem + SM_YSM);

    const int tid = threadIdx.x;
    const int wid = tid >> 5, lane = tid & 31;
    const int g = lane >> 2, tig = lane & 3;
    const int lm = lane >> 3, lr = lane & 7;   // ldmatrix: matrix id, row in matrix
    const int b = blockIdx.y;
    const int r = blockIdx.x * 2;
    const int mbase = (wid & 3) * 32;
    const int nb = (wid >> 2) * 64;

    const uint32_t sbase = smem_u32(smem);
    const uint32_t xh_base = sbase + SM_XH;
    const uint32_t xl_base = sbase + SM_XL;
    const int A_lane_off = (mbase + (lm & 1) * 8 + lr) * 144 + (lm >> 1) * 16;
    const int B_lane_off = (nb + lr) * 144 + lm * 16;

    if (tid < K_) biassm[tid] = bias[tid];

    // convert x rows r..r+3 (from NHWC g_xt, coalesced) -> bf16 hi/lo tiles
    {
        unsigned short* xhu = (unsigned short*)(smem + SM_XH);
        unsigned short* xlu = (unsigned short*)(smem + SM_XL);
        const int row = tid >> 6, w = tid & 63;
        const float4* xp = (const float4*)(g_xt + (((size_t)b * H_ + (r + row)) * H_ + w) * C_);
#pragma unroll
        for (int q = 0; q < 16; q++) {
            const float4 v4 = xp[q];
            const float vv[4] = {v4.x, v4.y, v4.z, v4.w};
#pragma unroll
            for (int u = 0; u < 4; u++) {
                const int c = q * 4 + u;
                __nv_bfloat16 hb = __float2bfloat16(vv[u]);
                __nv_bfloat16 lb = __float2bfloat16(vv[u] - __bfloat162float(hb));
                xhu[tid * 72 + c] = *(unsigned short*)&hb;
                xlu[tid * 72 + c] = *(unsigned short*)&lb;
            }
        }
    }

    float acc[2][8][4];
#pragma unroll
    for (int mt = 0; mt < 2; mt++)
#pragma unroll
        for (int nt = 0; nt < 8; nt++)
#pragma unroll
            for (int q = 0; q < 4; q++) acc[mt][nt][q] = 0.f;

    // stage slice 0 directly to buf0; prefetch slice 1 into regs
    {
        const uint4* gs = g_wa;
        uint4* d4 = (uint4*)(smem + SM_A);
#pragma unroll
        for (int q = 0; q < 5; q++) {
            const int idx = tid + 256 * q;
            if (idx < 1152) d4[idx] = gs[idx];
        }
    }
    uint4 pf[5];
    {
        const uint4* gs = g_wa + 1152;
#pragma unroll
        for (int q = 0; q < 5; q++) {
            const int idx = tid + 256 * q;
            if (idx < 1152) pf[q] = gs[idx];
        }
    }
    __syncthreads();   // covers B tiles + slice 0

    for (int s = 0; s < 18; s++) {
        const uint32_t acur = sbase + SM_A + (uint32_t)(s & 1) * 18432;
        // overlap: stage slice s+1 into the other buffer, prefetch s+2
        if (s < 17) {
            uint4* d4 = (uint4*)(smem + SM_A + ((s + 1) & 1) * 18432);
#pragma unroll
            for (int q = 0; q < 5; q++) {
                const int idx = tid + 256 * q;
                if (idx < 1152) d4[idx] = pf[q];
            }
            if (s < 16) {
                const uint4* gs = g_wa + (size_t)(s + 2) * 1152;
#pragma unroll
                for (int q = 0; q < 5; q++) {
                    const int idx = tid + 256 * q;
                    if (idx < 1152) pf[q] = gs[idx];
                }
            }
        }
        const int j = s / 6, i = (s % 6) >> 1, var = s & 1;
        do_pass_lm(acur, xh_base, A_lane_off, B_lane_off, i, acc);
        if (var == 0)
            do_pass_lm(acur, xl_base, A_lane_off, B_lane_off, i, acc);

        if ((s % 6) == 5) {  // end of j: dump D_j with column shift -j
#pragma unroll
            for (int mt = 0; mt < 2; mt++) {
                const int row0 = mbase + mt * 16 + g;
#pragma unroll
                for (int nt = 0; nt < 8; nt++) {
                    const int n0 = nb + nt * 8 + 2 * tig;
                    dump_one(ysm, row0,     n0,     acc[mt][nt][0], j);
                    dump_one(ysm, row0,     n0 + 1, acc[mt][nt][1], j);
                    dump_one(ysm, row0 + 8, n0,     acc[mt][nt][2], j);
                    dump_one(ysm, row0 + 8, n0 + 1, acc[mt][nt][3], j);
#pragma unroll
                    for (int q = 0; q < 4; q++) acc[mt][nt][q] = 0.f;
                }
            }
        }
        __syncthreads();   // slice boundary: STS(s+1) visible; readers done with acur
    }

    // argmax + ambiguity flag (values identical to y below)
    if (tid < 124) {
        const int orow = (tid >= 62) ? 1 : 0;
        const int w = tid - orow * 62;
        const int n = orow * 64 + w;
        float best = -3.402823466e38f, second = -3.402823466e38f;
        int bk = 0;
#pragma unroll 4
        for (int k = 0; k < K_; k++) {
            const float v = ysm[k * 132 + n] + biassm[k];
            if (v > best) { second = best; best = v; bk = k; }
            else if (v > second) second = v;
        }
        const int oh = r + orow;
        g_winner[b * (OH_ * OH_) + oh * OH_ + w] = bk;
        if (best - second < 1e-3f) {
            const int p = atomicAdd(&g_amb_cnt, 1);
            if (p < MAXAMB) g_amb[p] = (b << 12) | (oh << 6) | w;
        }
    }

    // coalesced y store: warp handles 32 (k,orow) rows; row = 62 contiguous floats
    {
#pragma unroll 4
        for (int rr = 0; rr < 32; rr++) {
            const int rowid = wid * 32 + rr;
            const int k = rowid >> 1, orow = rowid & 1;
            const float bk = biassm[k];
            float* ydst = y + (((size_t)b * K_ + k) * OH_ + (r + orow)) * OH_;
            const float* ysrc = ysm + k * 132 + orow * 64;
#pragma unroll
            for (int hh = 0; hh < 2; hh++) {
                const int w = hh * 32 + lane;
                if (w < OH_) ydst[w] = ysrc[w] + bk;
            }
        }
    }
}

// ---------------------------------------------------------------------------
// exact fp32 winner recompute for ambiguous locations (order matches the
// empirically-reference-matching round-2 scalar chain).
// ---------------------------------------------------------------------------
__global__ void fix_kernel(const float* __restrict__ y,
                           const float* __restrict__ bias) {
    int cnt = g_amb_cnt; if (cnt > MAXAMB) cnt = MAXAMB;
    const int gw = (blockIdx.x * blockDim.x + threadIdx.x) >> 5;
    const int lane = threadIdx.x & 31;
    const int nw = (gridDim.x * blockDim.x) >> 5;
    for (int e = gw; e < cnt; e += nw) {
        const int loc = g_amb[e];
        const int b = loc >> 12, oh = (loc >> 6) & 63, ow = loc & 63;
        float v[4];
#pragma unroll
        for (int q = 0; q < 4; q++)
            v[q] = y[((size_t)(b * K_ + q * 32 + lane) * OH_ + oh) * OH_ + ow];
        float m = fmaxf(fmaxf(v[0], v[1]), fmaxf(v[2], v[3]));
#pragma unroll
        for (int o = 16; o; o >>= 1) m = fmaxf(m, __shfl_xor_sync(0xffffffffu, m, o));

        float myval = -3.402823466e38f;
        int   myk   = 0x7fffffff;
        int cidx = 0;
#pragma unroll
        for (int q = 0; q < 4; q++) {
            unsigned mask = __ballot_sync(0xffffffffu, v[q] >= m - 1e-3f);
            while (mask) {
                const int src = __ffs(mask) - 1;
                mask &= mask - 1;
                const int k = q * 32 + src;
                if ((cidx & 31) == lane) {
                    const float* wk = g_wkt + k * 576;
                    const float* xb = g_xt + (((size_t)b * H_ + oh) * H_ + ow) * C_;
                    float s = 0.f;
                    for (int c = 0; c < C_; c++) {
                        const float* wc = wk + c * 9;
#pragma unroll
                        for (int i = 0; i < 3; i++) {
#pragma unroll
                            for (int j = 0; j < 3; j++)
                                s = fmaf(wc[i * 3 + j],
                                         xb[(i * H_ + j) * C_ + c], s);
                        }
                    }
                    const float val = s + bias[k];
                    if (val > myval || (val == myval && k < myk)) {
                        myval = val; myk = k;
                    }
                }
                cidx++;
            }
        }
#pragma unroll
        for (int o = 16; o; o >>= 1) {
            const float ov = __shfl_xor_sync(0xffffffffu, myval, o);
            const int   ok = __shfl_xor_sync(0xffffffffu, myk, o);
            if (ov > myval || (ov == myval && ok < myk)) { myval = ov; myk = ok; }
        }
        if (lane == 0) g_winner[b * (OH_ * OH_) + oh * OH_ + ow] = myk;
    }
}

// ---------------------------------------------------------------------------
// binning: hist / scan / block-aggregated scatter
// ---------------------------------------------------------------------------
__global__ void hist_kernel() {
    __shared__ int h[K_];
    const int tid = threadIdx.x;
    if (tid < K_) h[tid] = 0;
    __syncthreads();
    for (int i = blockIdx.x * blockDim.x + tid; i < LOCS; i += gridDim.x * blockDim.x)
        atomicAdd(&h[g_winner[i]], 1);
    __syncthreads();
    if (tid < K_ && h[tid]) atomicAdd(&g_counts[tid], h[tid]);
}

__global__ void scan_kernel() {
    __shared__ int s[K_];
    const int t = threadIdx.x;
    const int cnt = g_counts[t];
    s[t] = cnt;
    __syncthreads();
    for (int o = 1; o < K_; o <<= 1) {
        const int v = (t >= o) ? s[t - o] : 0;
        __syncthreads();
        s[t] += v;
        __syncthreads();
    }
    const int excl = s[t] - cnt;
    g_offs[t] = excl;
    g_cursor[t] = excl;
    if (t == K_ - 1) g_offs[K_] = s[K_ - 1];
}

// block-aggregated scatter: one global atomic per (block, k)
__global__ void scatter_kernel() {
    __shared__ int cnt[K_], base[K_], cur[K_];
    const int tid = threadIdx.x;
    const int per = (LOCS + gridDim.x - 1) / gridDim.x;
    const int s0 = blockIdx.x * per;
    int s1 = s0 + per; if (s1 > LOCS) s1 = LOCS;
    if (tid < K_) { cnt[tid] = 0; cur[tid] = 0; }
    __syncthreads();
    for (int idx = s0 + tid; idx < s1; idx += blockDim.x)
        atomicAdd(&cnt[g_winner[idx]], 1);
    __syncthreads();
    if (tid < K_)
        base[tid] = cnt[tid] ? atomicAdd(&g_cursor[tid], cnt[tid]) : 0;
    __syncthreads();
    for (int idx = s0 + tid; idx < s1; idx += blockDim.x) {
        const int k = g_winner[idx];
        const int off = atomicAdd(&cur[k], 1);
        const int b = idx / 3844, rem = idx % 3844;
        const int oh = rem / OH_, ow = rem % OH_;
        g_index[base[k] + off] = (b << 12) | (oh << 6) | ow;
    }
}

// ---------------------------------------------------------------------------
// hebb: NHWC gather, thread owns (tap, c-pair). grid (128 k, 4 chunks), 288 thr
// ---------------------------------------------------------------------------
__global__ void hebb_kernel(float* __restrict__ wu) {
    const int k = blockIdx.x, chunk = blockIdx.y;
    const int wid = threadIdx.x >> 5, lane = threadIdx.x & 31;
    const int i = wid / 3, j = wid % 3;
    const int start = g_offs[k], end = g_offs[k + 1];
    const int len = end - start;
    const int cs = start + (len * chunk) / 4;
    const int ce = start + (len * (chunk + 1)) / 4;
    float ax = 0.f, ay = 0.f;
    int p = cs;
    for (; p + 1 < ce; p += 2) {
        const int l0 = g_index[p], l1 = g_index[p + 1];
        const float2 v0 = *(const float2*)(g_xt +
            ((((l0 >> 12) * H_ + ((l0 >> 6) & 63) + i) * H_) + (l0 & 63) + j) * C_ + 2 * lane);
        const float2 v1 = *(const float2*)(g_xt +
            ((((l1 >> 12) * H_ + ((l1 >> 6) & 63) + i) * H_) + (l1 & 63) + j) * C_ + 2 * lane);
        ax += v0.x + v1.x; ay += v0.y + v1.y;
    }
    if (p < ce) {
        const int l0 = g_index[p];
        const float2 v0 = *(const float2*)(g_xt +
            ((((l0 >> 12) * H_ + ((l0 >> 6) & 63) + i) * H_) + (l0 & 63) + j) * C_ + 2 * lane);
        ax += v0.x; ay += v0.y;
    }
    const float sc = 1.f / 123008.f;
    atomicAdd(&wu[k * 576 + (2 * lane) * 9 + i * 3 + j], ax * sc);
    atomicAdd(&wu[k * 576 + (2 * lane + 1) * 9 + i * 3 + j], ay * sc);
}

// ---------------------------------------------------------------------------
extern "C" void kernel_launch(void* const* d_in, const int* in_sizes, int n_in,
                              void* d_out, int out_size) {
    const float* x    = (const float*)d_in[0];
    const float* w    = (const float*)d_in[1];
    const float* bias = (const float*)d_in[2];
    float* y  = (float*)d_out;
    float* wu = y + Y_ELEMS;

    cudaFuncSetAttribute(conv_mma_kernel,
                         cudaFuncAttributeMaxDynamicSharedMemorySize, SM_TOTAL);

    zero_kernel<<<72, 1024>>>(wu);
    transpose_kernel<<<dim3(64, 32), 256>>>(x);
    wnorm_kernel<<<K_, C_>>>(w);
    conv_mma_kernel<<<dim3(31, 32), 256, SM_TOTAL>>>(bias, y);
    fix_kernel<<<256, 128>>>(y, bias);
    hist_kernel<<<96, 256>>>();
    scan_kernel<<<1, K_>>>();
    scatter_kernel<<<96, 256>>>();
    hebb_kernel<<<dim3(K_, 4), 288>>>(wu);
}

// round 12
// speedup vs baseline: 1.8579x; 1.0332x over previous
#include <cuda_runtime.h>
#include <cuda_bf16.h>
#include <cstdint>

// Problem constants
#define B_   32
#define C_   64
#define K_   128
#define H_   64
#define OH_  62
#define LOCS 123008            // 32*62*62
#define Y_ELEMS 15745024       // 32*128*62*62
#define WU_ELEMS (K_ * C_ * 9)
#define MAXAMB 65536

// Static device scratch (no allocations allowed)
__device__ float g_xt[B_ * H_ * H_ * C_];   // x transposed to [b][h][w][c]
__device__ float g_wkt[K_ * C_ * 9];        // normalized weights [k][c][tap] fp32
__device__ uint4 g_wa[18 * 1152];           // 18 bf16 A slices [slice][k=128][72 bf16 padded]
__device__ int   g_winner[LOCS];
__device__ int   g_index[LOCS];
__device__ int   g_counts[K_];
__device__ int   g_offs[K_ + 1];
__device__ int   g_cursor[K_];
__device__ int   g_amb_cnt;
__device__ int   g_amb[MAXAMB];

// SMEM layout for conv (bytes) — A double-buffered
#define SM_BIAS 0
#define SM_XH   512
#define SM_XL   (512 + 36864)
#define SM_A    (512 + 2 * 36864)            // 2 x 18432
#define SM_YSM  (SM_A + 2 * 18432)
#define SM_TOTAL (SM_YSM + 128 * 132 * 4)    // 178688

__device__ __forceinline__ void mma_bf16(float* d, const uint32_t* a,
                                         uint32_t b0, uint32_t b1) {
    asm volatile(
        "mma.sync.aligned.m16n8k16.row.col.f32.bf16.bf16.f32 "
        "{%0,%1,%2,%3}, {%4,%5,%6,%7}, {%8,%9}, {%0,%1,%2,%3};"
        : "+f"(d[0]), "+f"(d[1]), "+f"(d[2]), "+f"(d[3])
        : "r"(a[0]), "r"(a[1]), "r"(a[2]), "r"(a[3]), "r"(b0), "r"(b1));
}
__device__ __forceinline__ void ldsm_x4(uint32_t* r, uint32_t addr) {
    asm volatile("ldmatrix.sync.aligned.m8n8.x4.shared.b16 {%0,%1,%2,%3}, [%4];"
        : "=r"(r[0]), "=r"(r[1]), "=r"(r[2]), "=r"(r[3]) : "r"(addr));
}
__device__ __forceinline__ uint32_t smem_u32(const void* p) {
    return (uint32_t)__cvta_generic_to_shared(p);
}

// ---------------------------------------------------------------------------
// merged zero kernel
// ---------------------------------------------------------------------------
__global__ void zero_kernel(float* wu) {
    const int i = blockIdx.x * 1024 + threadIdx.x;
    if (i < WU_ELEMS) wu[i] = 0.f;
    if (blockIdx.x == 0) {
        if (threadIdx.x < K_) g_counts[threadIdx.x] = 0;
        if (threadIdx.x == 0) g_amb_cnt = 0;
    }
}

// ---------------------------------------------------------------------------
// transpose x -> [b][h][w][c]
// ---------------------------------------------------------------------------
__global__ void transpose_kernel(const float* __restrict__ x) {
    __shared__ float tile[64][65];
    const int h = blockIdx.x, b = blockIdx.y, tid = threadIdx.x;
    for (int idx = tid; idx < 4096; idx += 256) {
        const int c = idx >> 6, w = idx & 63;
        tile[c][w] = x[((b * C_ + c) * H_ + h) * H_ + w];
    }
    __syncthreads();
    for (int idx = tid; idx < 4096; idx += 256) {
        const int w = idx >> 6, c = idx & 63;
        g_xt[((b * H_ + h) * H_ + w) * C_ + c] = tile[c][w];
    }
}

// ---------------------------------------------------------------------------
// weight normalization -> g_wkt fp32 + 18 bf16 hi/lo A slices
// slice = j*6 + i*2 + var
// ---------------------------------------------------------------------------
__global__ void wnorm_kernel(const float* __restrict__ w) {
    const int k = blockIdx.x, c = threadIdx.x;
    const float* wp = w + (k * C_ + c) * 9;
    float v[9];
    float ssq = 0.f;
#pragma unroll
    for (int t = 0; t < 9; t++) { v[t] = wp[t]; ssq += v[t] * v[t]; }
#pragma unroll
    for (int o = 16; o; o >>= 1) ssq += __shfl_down_sync(0xffffffffu, ssq, o);
    __shared__ float red[2];
    if ((c & 31) == 0) red[c >> 5] = ssq;
    __syncthreads();
    const float total = red[0] + red[1];
    const float inv = (total == 0.f) ? 1.f : (1.f / sqrtf(total));
    unsigned short* wa = (unsigned short*)g_wa;
#pragma unroll
    for (int t = 0; t < 9; t++) {
        const float wn = v[t] * inv;
        g_wkt[k * 576 + c * 9 + t] = wn;
        const int i = t / 3, j = t % 3;
        __nv_bfloat16 hb = __float2bfloat16(wn);
        __nv_bfloat16 lb = __float2bfloat16(wn - __bfloat162float(hb));
        const int s0 = j * 6 + i * 2;
        wa[(s0)     * 9216 + k * 72 + c] = *(unsigned short*)&hb;
        wa[(s0 + 1) * 9216 + k * 72 + c] = *(unsigned short*)&lb;
    }
}

// ---------------------------------------------------------------------------
// conv: mma.sync bf16 3-term split, ldmatrix, double-buffered A,
// 512 threads / 16 warps (warp tile 32k x 32n) for occupancy
// ---------------------------------------------------------------------------
__device__ __forceinline__ void do_pass_lm(uint32_t abase, uint32_t xbase,
                                           int A_lane_off, int B_lane_off,
                                           int i, float acc[2][4][4]) {
#pragma unroll
    for (int kh = 0; kh < 2; kh++) {
        uint32_t Breg[4][4];
#pragma unroll
        for (int nt = 0; nt < 4; nt++)
            ldsm_x4(Breg[nt], xbase + B_lane_off + (i * 64 + nt * 8) * 144 + kh * 64);
        uint32_t Areg[2][2][4];
#pragma unroll
        for (int mt = 0; mt < 2; mt++)
#pragma unroll
            for (int kl = 0; kl < 2; kl++)
                ldsm_x4(Areg[mt][kl], abase + A_lane_off + mt * 2304 + (kh * 2 + kl) * 32);
#pragma unroll
        for (int kl = 0; kl < 2; kl++)
#pragma unroll
            for (int nt = 0; nt < 4; nt++) {
                mma_bf16(acc[0][nt], Areg[0][kl], Breg[nt][kl * 2], Breg[nt][kl * 2 + 1]);
                mma_bf16(acc[1][nt], Areg[1][kl], Breg[nt][kl * 2], Breg[nt][kl * 2 + 1]);
            }
    }
}

__device__ __forceinline__ void dump_one(float* ysm, int row, int n, float v, int j) {
    const int w = n & 63;
    if (w >= j) {
        const int idx = row * 132 + n - j;
        if (j == 0) ysm[idx] = v;
        else        ysm[idx] += v;
    }
}

__global__ __launch_bounds__(512, 1)
void conv_mma_kernel(const float* __restrict__ bias,
                     float* __restrict__ y) {
    extern __shared__ char smem[];
    float*    biassm = (float*)(smem + SM_BIAS);
    float*    ysm = (float*)(smem + SM_YSM);

    const int tid = threadIdx.x;
    const int wid = tid >> 5, lane = tid & 31;
    const int g = lane >> 2, tig = lane & 3;
    const int lm = lane >> 3, lr = lane & 7;   // ldmatrix: matrix id, row in matrix
    const int b = blockIdx.y;
    const int r = blockIdx.x * 2;
    const int mbase = (wid & 3) * 32;          // 4 m-groups
    const int nb = (wid >> 2) * 32;            // 4 n-groups

    const uint32_t sbase = smem_u32(smem);
    const uint32_t xh_base = sbase + SM_XH;
    const uint32_t xl_base = sbase + SM_XL;
    const int A_lane_off = (mbase + (lm & 1) * 8 + lr) * 144 + (lm >> 1) * 16;
    const int B_lane_off = (nb + lr) * 144 + lm * 16;

    if (tid < K_) biassm[tid] = bias[tid];

    // convert x rows r..r+3 -> bf16 hi/lo tiles; 512 threads: (n', c-half)
    {
        unsigned short* xhu = (unsigned short*)(smem + SM_XH);
        unsigned short* xlu = (unsigned short*)(smem + SM_XL);
        const int np = tid & 255;               // n' row 0..255
        const int chalf = tid >> 8;             // 0 or 1 (32 c each)
        const int row = np >> 6, w = np & 63;
        const float4* xp = (const float4*)(g_xt +
            (((size_t)b * H_ + (r + row)) * H_ + w) * C_ + chalf * 32);
#pragma unroll
        for (int q = 0; q < 8; q++) {
            const float4 v4 = xp[q];
            const float vv[4] = {v4.x, v4.y, v4.z, v4.w};
#pragma unroll
            for (int u = 0; u < 4; u++) {
                const int c = chalf * 32 + q * 4 + u;
                __nv_bfloat16 hb = __float2bfloat16(vv[u]);
                __nv_bfloat16 lb = __float2bfloat16(vv[u] - __bfloat162float(hb));
                xhu[np * 72 + c] = *(unsigned short*)&hb;
                xlu[np * 72 + c] = *(unsigned short*)&lb;
            }
        }
    }

    float acc[2][4][4];
#pragma unroll
    for (int mt = 0; mt < 2; mt++)
#pragma unroll
        for (int nt = 0; nt < 4; nt++)
#pragma unroll
            for (int q = 0; q < 4; q++) acc[mt][nt][q] = 0.f;

    // stage slice 0 to buf0; prefetch slice 1 into regs
    {
        const uint4* gs = g_wa;
        uint4* d4 = (uint4*)(smem + SM_A);
#pragma unroll
        for (int q = 0; q < 3; q++) {
            const int idx = tid + 512 * q;
            if (idx < 1152) d4[idx] = gs[idx];
        }
    }
    uint4 pf[3];
    {
        const uint4* gs = g_wa + 1152;
#pragma unroll
        for (int q = 0; q < 3; q++) {
            const int idx = tid + 512 * q;
            if (idx < 1152) pf[q] = gs[idx];
        }
    }
    __syncthreads();   // covers B tiles + slice 0

    for (int s = 0; s < 18; s++) {
        const uint32_t acur = sbase + SM_A + (uint32_t)(s & 1) * 18432;
        // overlap: stage slice s+1 into other buffer, prefetch s+2
        if (s < 17) {
            uint4* d4 = (uint4*)(smem + SM_A + ((s + 1) & 1) * 18432);
#pragma unroll
            for (int q = 0; q < 3; q++) {
                const int idx = tid + 512 * q;
                if (idx < 1152) d4[idx] = pf[q];
            }
            if (s < 16) {
                const uint4* gs = g_wa + (size_t)(s + 2) * 1152;
#pragma unroll
                for (int q = 0; q < 3; q++) {
                    const int idx = tid + 512 * q;
                    if (idx < 1152) pf[q] = gs[idx];
                }
            }
        }
        const int j = s / 6, i = (s % 6) >> 1, var = s & 1;
        do_pass_lm(acur, xh_base, A_lane_off, B_lane_off, i, acc);
        if (var == 0)
            do_pass_lm(acur, xl_base, A_lane_off, B_lane_off, i, acc);

        if ((s % 6) == 5) {  // end of j: dump D_j with column shift -j
#pragma unroll
            for (int mt = 0; mt < 2; mt++) {
                const int row0 = mbase + mt * 16 + g;
#pragma unroll
                for (int nt = 0; nt < 4; nt++) {
                    const int n0 = nb + nt * 8 + 2 * tig;
                    dump_one(ysm, row0,     n0,     acc[mt][nt][0], j);
                    dump_one(ysm, row0,     n0 + 1, acc[mt][nt][1], j);
                    dump_one(ysm, row0 + 8, n0,     acc[mt][nt][2], j);
                    dump_one(ysm, row0 + 8, n0 + 1, acc[mt][nt][3], j);
#pragma unroll
                    for (int q = 0; q < 4; q++) acc[mt][nt][q] = 0.f;
                }
            }
        }
        __syncthreads();   // slice boundary
    }

    // argmax + ambiguity flag (values identical to y below)
    if (tid < 124) {
        const int orow = (tid >= 62) ? 1 : 0;
        const int w = tid - orow * 62;
        const int n = orow * 64 + w;
        float best = -3.402823466e38f, second = -3.402823466e38f;
        int bk = 0;
#pragma unroll 4
        for (int k = 0; k < K_; k++) {
            const float v = ysm[k * 132 + n] + biassm[k];
            if (v > best) { second = best; best = v; bk = k; }
            else if (v > second) second = v;
        }
        const int oh = r + orow;
        g_winner[b * (OH_ * OH_) + oh * OH_ + w] = bk;
        if (best - second < 1e-3f) {
            const int p = atomicAdd(&g_amb_cnt, 1);
            if (p < MAXAMB) g_amb[p] = (b << 12) | (oh << 6) | w;
        }
    }

    // coalesced y store: 16 warps x 16 (k,orow) rows
    {
#pragma unroll 4
        for (int rr = 0; rr < 16; rr++) {
            const int rowid = wid * 16 + rr;
            const int k = rowid >> 1, orow = rowid & 1;
            const float bk = biassm[k];
            float* ydst = y + (((size_t)b * K_ + k) * OH_ + (r + orow)) * OH_;
            const float* ysrc = ysm + k * 132 + orow * 64;
#pragma unroll
            for (int hh = 0; hh < 2; hh++) {
                const int w = hh * 32 + lane;
                if (w < OH_) ydst[w] = ysrc[w] + bk;
            }
        }
    }
}

// ---------------------------------------------------------------------------
// exact fp32 winner recompute for ambiguous locations (order matches the
// empirically-reference-matching round-2 scalar chain).
// ---------------------------------------------------------------------------
__global__ void fix_kernel(const float* __restrict__ y,
                           const float* __restrict__ bias) {
    int cnt = g_amb_cnt; if (cnt > MAXAMB) cnt = MAXAMB;
    const int gw = (blockIdx.x * blockDim.x + threadIdx.x) >> 5;
    const int lane = threadIdx.x & 31;
    const int nw = (gridDim.x * blockDim.x) >> 5;
    for (int e = gw; e < cnt; e += nw) {
        const int loc = g_amb[e];
        const int b = loc >> 12, oh = (loc >> 6) & 63, ow = loc & 63;
        float v[4];
#pragma unroll
        for (int q = 0; q < 4; q++)
            v[q] = y[((size_t)(b * K_ + q * 32 + lane) * OH_ + oh) * OH_ + ow];
        float m = fmaxf(fmaxf(v[0], v[1]), fmaxf(v[2], v[3]));
#pragma unroll
        for (int o = 16; o; o >>= 1) m = fmaxf(m, __shfl_xor_sync(0xffffffffu, m, o));

        float myval = -3.402823466e38f;
        int   myk   = 0x7fffffff;
        int cidx = 0;
#pragma unroll
        for (int q = 0; q < 4; q++) {
            unsigned mask = __ballot_sync(0xffffffffu, v[q] >= m - 1e-3f);
            while (mask) {
                const int src = __ffs(mask) - 1;
                mask &= mask - 1;
                const int k = q * 32 + src;
                if ((cidx & 31) == lane) {
                    const float* wk = g_wkt + k * 576;
                    const float* xb = g_xt + (((size_t)b * H_ + oh) * H_ + ow) * C_;
                    float s = 0.f;
                    for (int c = 0; c < C_; c++) {
                        const float* wc = wk + c * 9;
#pragma unroll
                        for (int i = 0; i < 3; i++) {
#pragma unroll
                            for (int j = 0; j < 3; j++)
                                s = fmaf(wc[i * 3 + j],
                                         xb[(i * H_ + j) * C_ + c], s);
                        }
                    }
                    const float val = s + bias[k];
                    if (val > myval || (val == myval && k < myk)) {
                        myval = val; myk = k;
                    }
                }
                cidx++;
            }
        }
#pragma unroll
        for (int o = 16; o; o >>= 1) {
            const float ov = __shfl_xor_sync(0xffffffffu, myval, o);
            const int   ok = __shfl_xor_sync(0xffffffffu, myk, o);
            if (ov > myval || (ov == myval && ok < myk)) { myval = ov; myk = ok; }
        }
        if (lane == 0) g_winner[b * (OH_ * OH_) + oh * OH_ + ow] = myk;
    }
}

// ---------------------------------------------------------------------------
// binning: hist / scan / block-aggregated scatter
// ---------------------------------------------------------------------------
__global__ void hist_kernel() {
    __shared__ int h[K_];
    const int tid = threadIdx.x;
    if (tid < K_) h[tid] = 0;
    __syncthreads();
    for (int i = blockIdx.x * blockDim.x + tid; i < LOCS; i += gridDim.x * blockDim.x)
        atomicAdd(&h[g_winner[i]], 1);
    __syncthreads();
    if (tid < K_ && h[tid]) atomicAdd(&g_counts[tid], h[tid]);
}

__global__ void scan_kernel() {
    __shared__ int s[K_];
    const int t = threadIdx.x;
    const int cnt = g_counts[t];
    s[t] = cnt;
    __syncthreads();
    for (int o = 1; o < K_; o <<= 1) {
        const int v = (t >= o) ? s[t - o] : 0;
        __syncthreads();
        s[t] += v;
        __syncthreads();
    }
    const int excl = s[t] - cnt;
    g_offs[t] = excl;
    g_cursor[t] = excl;
    if (t == K_ - 1) g_offs[K_] = s[K_ - 1];
}

// block-aggregated scatter: one global atomic per (block, k)
__global__ void scatter_kernel() {
    __shared__ int cnt[K_], base[K_], cur[K_];
    const int tid = threadIdx.x;
    const int per = (LOCS + gridDim.x - 1) / gridDim.x;
    const int s0 = blockIdx.x * per;
    int s1 = s0 + per; if (s1 > LOCS) s1 = LOCS;
    if (tid < K_) { cnt[tid] = 0; cur[tid] = 0; }
    __syncthreads();
    for (int idx = s0 + tid; idx < s1; idx += blockDim.x)
        atomicAdd(&cnt[g_winner[idx]], 1);
    __syncthreads();
    if (tid < K_)
        base[tid] = cnt[tid] ? atomicAdd(&g_cursor[tid], cnt[tid]) : 0;
    __syncthreads();
    for (int idx = s0 + tid; idx < s1; idx += blockDim.x) {
        const int k = g_winner[idx];
        const int off = atomicAdd(&cur[k], 1);
        const int b = idx / 3844, rem = idx % 3844;
        const int oh = rem / OH_, ow = rem % OH_;
        g_index[base[k] + off] = (b << 12) | (oh << 6) | ow;
    }
}

// ---------------------------------------------------------------------------
// hebb: NHWC gather, thread owns (tap, c-pair). grid (128 k, 4 chunks), 288 thr
// ---------------------------------------------------------------------------
__global__ void hebb_kernel(float* __restrict__ wu) {
    const int k = blockIdx.x, chunk = blockIdx.y;
    const int wid = threadIdx.x >> 5, lane = threadIdx.x & 31;
    const int i = wid / 3, j = wid % 3;
    const int start = g_offs[k], end = g_offs[k + 1];
    const int len = end - start;
    const int cs = start + (len * chunk) / 4;
    const int ce = start + (len * (chunk + 1)) / 4;
    float ax = 0.f, ay = 0.f;
    int p = cs;
    for (; p + 1 < ce; p += 2) {
        const int l0 = g_index[p], l1 = g_index[p + 1];
        const float2 v0 = *(const float2*)(g_xt +
            ((((l0 >> 12) * H_ + ((l0 >> 6) & 63) + i) * H_) + (l0 & 63) + j) * C_ + 2 * lane);
        const float2 v1 = *(const float2*)(g_xt +
            ((((l1 >> 12) * H_ + ((l1 >> 6) & 63) + i) * H_) + (l1 & 63) + j) * C_ + 2 * lane);
        ax += v0.x + v1.x; ay += v0.y + v1.y;
    }
    if (p < ce) {
        const int l0 = g_index[p];
        const float2 v0 = *(const float2*)(g_xt +
            ((((l0 >> 12) * H_ + ((l0 >> 6) & 63) + i) * H_) + (l0 & 63) + j) * C_ + 2 * lane);
        ax += v0.x; ay += v0.y;
    }
    const float sc = 1.f / 123008.f;
    atomicAdd(&wu[k * 576 + (2 * lane) * 9 + i * 3 + j], ax * sc);
    atomicAdd(&wu[k * 576 + (2 * lane + 1) * 9 + i * 3 + j], ay * sc);
}

// ---------------------------------------------------------------------------
extern "C" void kernel_launch(void* const* d_in, const int* in_sizes, int n_in,
                              void* d_out, int out_size) {
    const float* x    = (const float*)d_in[0];
    const float* w    = (const float*)d_in[1];
    const float* bias = (const float*)d_in[2];
    float* y  = (float*)d_out;
    float* wu = y + Y_ELEMS;

    cudaFuncSetAttribute(conv_mma_kernel,
                         cudaFuncAttributeMaxDynamicSharedMemorySize, SM_TOTAL);

    zero_kernel<<<72, 1024>>>(wu);
    transpose_kernel<<<dim3(64, 32), 256>>>(x);
    wnorm_kernel<<<K_, C_>>>(w);
    conv_mma_kernel<<<dim3(31, 32), 512, SM_TOTAL>>>(bias, y);
    fix_kernel<<<256, 128>>>(y, bias);
    hist_kernel<<<96, 256>>>();
    scan_kernel<<<1, K_>>>();
    scatter_kernel<<<96, 256>>>();
    hebb_kernel<<<dim3(K_, 4), 288>>>(wu);
}

// round 13
// speedup vs baseline: 2.0865x; 1.1231x over previous
#include <cuda_runtime.h>
#include <cuda_fp16.h>
#include <cstdint>

// Problem constants
#define B_   32
#define C_   64
#define K_   128
#define H_   64
#define OH_  62
#define LOCS 123008            // 32*62*62
#define Y_ELEMS 15745024       // 32*128*62*62
#define WU_ELEMS (K_ * C_ * 9)
#define MAXAMB 65536

// Static device scratch (no allocations allowed)
__device__ float g_xt[B_ * H_ * H_ * C_];   // x transposed to [b][h][w][c]
__device__ float g_wkt[K_ * C_ * 9];        // normalized weights [k][c][tap] fp32
__device__ uint4 g_wa[18 * 1152];           // 18 fp16 A slices [slice][k=128][72 fp16 padded]
__device__ int   g_winner[LOCS];
__device__ int   g_index[LOCS];
__device__ int   g_counts[K_];
__device__ int   g_offs[K_ + 1];
__device__ int   g_cursor[K_];
__device__ int   g_amb_cnt;
__device__ int   g_amb[MAXAMB];

// SMEM layout for conv (bytes) — xh tile only, A double-buffered
#define SM_BIAS 0
#define SM_XH   512
#define SM_A    (512 + 36864)                // 2 x 18432
#define SM_YSM  (SM_A + 2 * 18432)
#define SM_TOTAL (SM_YSM + 128 * 132 * 4)    // 141824

__device__ __forceinline__ void mma_f16(float* d, const uint32_t* a,
                                        uint32_t b0, uint32_t b1) {
    asm volatile(
        "mma.sync.aligned.m16n8k16.row.col.f32.f16.f16.f32 "
        "{%0,%1,%2,%3}, {%4,%5,%6,%7}, {%8,%9}, {%0,%1,%2,%3};"
        : "+f"(d[0]), "+f"(d[1]), "+f"(d[2]), "+f"(d[3])
        : "r"(a[0]), "r"(a[1]), "r"(a[2]), "r"(a[3]), "r"(b0), "r"(b1));
}
__device__ __forceinline__ void ldsm_x4(uint32_t* r, uint32_t addr) {
    asm volatile("ldmatrix.sync.aligned.m8n8.x4.shared.b16 {%0,%1,%2,%3}, [%4];"
        : "=r"(r[0]), "=r"(r[1]), "=r"(r[2]), "=r"(r[3]) : "r"(addr));
}
__device__ __forceinline__ uint32_t smem_u32(const void* p) {
    return (uint32_t)__cvta_generic_to_shared(p);
}

// ---------------------------------------------------------------------------
// merged zero kernel
// ---------------------------------------------------------------------------
__global__ void zero_kernel(float* wu) {
    const int i = blockIdx.x * 1024 + threadIdx.x;
    if (i < WU_ELEMS) wu[i] = 0.f;
    if (blockIdx.x == 0) {
        if (threadIdx.x < K_) g_counts[threadIdx.x] = 0;
        if (threadIdx.x == 0) g_amb_cnt = 0;
    }
}

// ---------------------------------------------------------------------------
// transpose x -> [b][h][w][c]
// ---------------------------------------------------------------------------
__global__ void transpose_kernel(const float* __restrict__ x) {
    __shared__ float tile[64][65];
    const int h = blockIdx.x, b = blockIdx.y, tid = threadIdx.x;
    for (int idx = tid; idx < 4096; idx += 256) {
        const int c = idx >> 6, w = idx & 63;
        tile[c][w] = x[((b * C_ + c) * H_ + h) * H_ + w];
    }
    __syncthreads();
    for (int idx = tid; idx < 4096; idx += 256) {
        const int w = idx >> 6, c = idx & 63;
        g_xt[((b * H_ + h) * H_ + w) * C_ + c] = tile[c][w];
    }
}

// ---------------------------------------------------------------------------
// weight normalization -> g_wkt fp32 + 18 fp16 A slices (whi/wlo per tap)
// slice = j*6 + i*2 + var  (var 0 = whi, 1 = wlo)
// ---------------------------------------------------------------------------
__global__ void wnorm_kernel(const float* __restrict__ w) {
    const int k = blockIdx.x, c = threadIdx.x;
    const float* wp = w + (k * C_ + c) * 9;
    float v[9];
    float ssq = 0.f;
#pragma unroll
    for (int t = 0; t < 9; t++) { v[t] = wp[t]; ssq += v[t] * v[t]; }
#pragma unroll
    for (int o = 16; o; o >>= 1) ssq += __shfl_down_sync(0xffffffffu, ssq, o);
    __shared__ float red[2];
    if ((c & 31) == 0) red[c >> 5] = ssq;
    __syncthreads();
    const float total = red[0] + red[1];
    const float inv = (total == 0.f) ? 1.f : (1.f / sqrtf(total));
    unsigned short* wa = (unsigned short*)g_wa;
#pragma unroll
    for (int t = 0; t < 9; t++) {
        const float wn = v[t] * inv;
        g_wkt[k * 576 + c * 9 + t] = wn;
        const int i = t / 3, j = t % 3;
        __half hb = __float2half(wn);
        __half lb = __float2half(wn - __half2float(hb));
        const int s0 = j * 6 + i * 2;
        wa[(s0)     * 9216 + k * 72 + c] = *(unsigned short*)&hb;
        wa[(s0 + 1) * 9216 + k * 72 + c] = *(unsigned short*)&lb;
    }
}

// ---------------------------------------------------------------------------
// conv: mma.sync fp16 2-term split, ldmatrix, double-buffered A, 512 threads
// ---------------------------------------------------------------------------
__device__ __forceinline__ void do_pass_lm(uint32_t abase, uint32_t xbase,
                                           int A_lane_off, int B_lane_off,
                                           int i, float acc[2][4][4]) {
#pragma unroll
    for (int kh = 0; kh < 2; kh++) {
        uint32_t Breg[4][4];
#pragma unroll
        for (int nt = 0; nt < 4; nt++)
            ldsm_x4(Breg[nt], xbase + B_lane_off + (i * 64 + nt * 8) * 144 + kh * 64);
        uint32_t Areg[2][2][4];
#pragma unroll
        for (int mt = 0; mt < 2; mt++)
#pragma unroll
            for (int kl = 0; kl < 2; kl++)
                ldsm_x4(Areg[mt][kl], abase + A_lane_off + mt * 2304 + (kh * 2 + kl) * 32);
#pragma unroll
        for (int kl = 0; kl < 2; kl++)
#pragma unroll
            for (int nt = 0; nt < 4; nt++) {
                mma_f16(acc[0][nt], Areg[0][kl], Breg[nt][kl * 2], Breg[nt][kl * 2 + 1]);
                mma_f16(acc[1][nt], Areg[1][kl], Breg[nt][kl * 2], Breg[nt][kl * 2 + 1]);
            }
    }
}

__device__ __forceinline__ void dump_one(float* ysm, int row, int n, float v, int j) {
    const int w = n & 63;
    if (w >= j) {
        const int idx = row * 132 + n - j;
        if (j == 0) ysm[idx] = v;
        else        ysm[idx] += v;
    }
}

__global__ __launch_bounds__(512, 1)
void conv_mma_kernel(const float* __restrict__ bias,
                     float* __restrict__ y) {
    extern __shared__ char smem[];
    float*    biassm = (float*)(smem + SM_BIAS);
    float*    ysm = (float*)(smem + SM_YSM);

    const int tid = threadIdx.x;
    const int wid = tid >> 5, lane = tid & 31;
    const int g = lane >> 2, tig = lane & 3;
    const int lm = lane >> 3, lr = lane & 7;
    const int b = blockIdx.y;
    const int r = blockIdx.x * 2;
    const int mbase = (wid & 3) * 32;          // 4 m-groups
    const int nb = (wid >> 2) * 32;            // 4 n-groups

    const uint32_t sbase = smem_u32(smem);
    const uint32_t xh_base = sbase + SM_XH;
    const int A_lane_off = (mbase + (lm & 1) * 8 + lr) * 144 + (lm >> 1) * 16;
    const int B_lane_off = (nb + lr) * 144 + lm * 16;

    if (tid < K_) biassm[tid] = bias[tid];

    // convert x rows r..r+3 -> fp16 tile; 512 threads: (n', c-half)
    {
        unsigned short* xhu = (unsigned short*)(smem + SM_XH);
        const int np = tid & 255;               // n' row 0..255
        const int chalf = tid >> 8;             // 0 or 1 (32 c each)
        const int row = np >> 6, w = np & 63;
        const float4* xp = (const float4*)(g_xt +
            (((size_t)b * H_ + (r + row)) * H_ + w) * C_ + chalf * 32);
#pragma unroll
        for (int q = 0; q < 8; q++) {
            const float4 v4 = xp[q];
            const float vv[4] = {v4.x, v4.y, v4.z, v4.w};
#pragma unroll
            for (int u = 0; u < 4; u++) {
                const int c = chalf * 32 + q * 4 + u;
                __half hb = __float2half(vv[u]);
                xhu[np * 72 + c] = *(unsigned short*)&hb;
            }
        }
    }

    float acc[2][4][4];
#pragma unroll
    for (int mt = 0; mt < 2; mt++)
#pragma unroll
        for (int nt = 0; nt < 4; nt++)
#pragma unroll
            for (int q = 0; q < 4; q++) acc[mt][nt][q] = 0.f;

    // stage slice 0 to buf0; prefetch slice 1 into regs
    {
        const uint4* gs = g_wa;
        uint4* d4 = (uint4*)(smem + SM_A);
#pragma unroll
        for (int q = 0; q < 3; q++) {
            const int idx = tid + 512 * q;
            if (idx < 1152) d4[idx] = gs[idx];
        }
    }
    uint4 pf[3];
    {
        const uint4* gs = g_wa + 1152;
#pragma unroll
        for (int q = 0; q < 3; q++) {
            const int idx = tid + 512 * q;
            if (idx < 1152) pf[q] = gs[idx];
        }
    }
    __syncthreads();   // covers B tile + slice 0

    for (int s = 0; s < 18; s++) {
        const uint32_t acur = sbase + SM_A + (uint32_t)(s & 1) * 18432;
        // overlap: stage slice s+1 into other buffer, prefetch s+2
        if (s < 17) {
            uint4* d4 = (uint4*)(smem + SM_A + ((s + 1) & 1) * 18432);
#pragma unroll
            for (int q = 0; q < 3; q++) {
                const int idx = tid + 512 * q;
                if (idx < 1152) d4[idx] = pf[q];
            }
            if (s < 16) {
                const uint4* gs = g_wa + (size_t)(s + 2) * 1152;
#pragma unroll
                for (int q = 0; q < 3; q++) {
                    const int idx = tid + 512 * q;
                    if (idx < 1152) pf[q] = gs[idx];
                }
            }
        }
        const int j = s / 6, i = (s % 6) >> 1;   // var implicit: whi/wlo both just mma with xh
        do_pass_lm(acur, xh_base, A_lane_off, B_lane_off, i, acc);

        if ((s % 6) == 5) {  // end of j: dump D_j with column shift -j
#pragma unroll
            for (int mt = 0; mt < 2; mt++) {
                const int row0 = mbase + mt * 16 + g;
#pragma unroll
                for (int nt = 0; nt < 4; nt++) {
                    const int n0 = nb + nt * 8 + 2 * tig;
                    dump_one(ysm, row0,     n0,     acc[mt][nt][0], j);
                    dump_one(ysm, row0,     n0 + 1, acc[mt][nt][1], j);
                    dump_one(ysm, row0 + 8, n0,     acc[mt][nt][2], j);
                    dump_one(ysm, row0 + 8, n0 + 1, acc[mt][nt][3], j);
#pragma unroll
                    for (int q = 0; q < 4; q++) acc[mt][nt][q] = 0.f;
                }
            }
        }
        __syncthreads();   // slice boundary
    }

    // argmax + ambiguity flag (widened margin for fp16 2-term y error)
    if (tid < 124) {
        const int orow = (tid >= 62) ? 1 : 0;
        const int w = tid - orow * 62;
        const int n = orow * 64 + w;
        float best = -3.402823466e38f, second = -3.402823466e38f;
        int bk = 0;
#pragma unroll 4
        for (int k = 0; k < K_; k++) {
            const float v = ysm[k * 132 + n] + biassm[k];
            if (v > best) { second = best; best = v; bk = k; }
            else if (v > second) second = v;
        }
        const int oh = r + orow;
        g_winner[b * (OH_ * OH_) + oh * OH_ + w] = bk;
        if (best - second < 2.5e-3f) {
            const int p = atomicAdd(&g_amb_cnt, 1);
            if (p < MAXAMB) g_amb[p] = (b << 12) | (oh << 6) | w;
        }
    }

    // coalesced y store: 16 warps x 16 (k,orow) rows
    {
#pragma unroll 4
        for (int rr = 0; rr < 16; rr++) {
            const int rowid = wid * 16 + rr;
            const int k = rowid >> 1, orow = rowid & 1;
            const float bk = biassm[k];
            float* ydst = y + (((size_t)b * K_ + k) * OH_ + (r + orow)) * OH_;
            const float* ysrc = ysm + k * 132 + orow * 64;
#pragma unroll
            for (int hh = 0; hh < 2; hh++) {
                const int w = hh * 32 + lane;
                if (w < OH_) ydst[w] = ysrc[w] + bk;
            }
        }
    }
}

// ---------------------------------------------------------------------------
// exact fp32 winner recompute for ambiguous locations (order matches the
// empirically-reference-matching round-2 scalar chain).
// ---------------------------------------------------------------------------
__global__ void fix_kernel(const float* __restrict__ y,
                           const float* __restrict__ bias) {
    int cnt = g_amb_cnt; if (cnt > MAXAMB) cnt = MAXAMB;
    const int gw = (blockIdx.x * blockDim.x + threadIdx.x) >> 5;
    const int lane = threadIdx.x & 31;
    const int nw = (gridDim.x * blockDim.x) >> 5;
    for (int e = gw; e < cnt; e += nw) {
        const int loc = g_amb[e];
        const int b = loc >> 12, oh = (loc >> 6) & 63, ow = loc & 63;
        float v[4];
#pragma unroll
        for (int q = 0; q < 4; q++)
            v[q] = y[((size_t)(b * K_ + q * 32 + lane) * OH_ + oh) * OH_ + ow];
        float m = fmaxf(fmaxf(v[0], v[1]), fmaxf(v[2], v[3]));
#pragma unroll
        for (int o = 16; o; o >>= 1) m = fmaxf(m, __shfl_xor_sync(0xffffffffu, m, o));

        float myval = -3.402823466e38f;
        int   myk   = 0x7fffffff;
        int cidx = 0;
#pragma unroll
        for (int q = 0; q < 4; q++) {
            unsigned mask = __ballot_sync(0xffffffffu, v[q] >= m - 2.5e-3f);
            while (mask) {
                const int src = __ffs(mask) - 1;
                mask &= mask - 1;
                const int k = q * 32 + src;
                if ((cidx & 31) == lane) {
                    const float* wk = g_wkt + k * 576;
                    const float* xb = g_xt + (((size_t)b * H_ + oh) * H_ + ow) * C_;
                    float s = 0.f;
                    for (int c = 0; c < C_; c++) {
                        const float* wc = wk + c * 9;
#pragma unroll
                        for (int i = 0; i < 3; i++) {
#pragma unroll
                            for (int j = 0; j < 3; j++)
                                s = fmaf(wc[i * 3 + j],
                                         xb[(i * H_ + j) * C_ + c], s);
                        }
                    }
                    const float val = s + bias[k];
                    if (val > myval || (val == myval && k < myk)) {
                        myval = val; myk = k;
                    }
                }
                cidx++;
            }
        }
#pragma unroll
        for (int o = 16; o; o >>= 1) {
            const float ov = __shfl_xor_sync(0xffffffffu, myval, o);
            const int   ok = __shfl_xor_sync(0xffffffffu, myk, o);
            if (ov > myval || (ov == myval && ok < myk)) { myval = ov; myk = ok; }
        }
        if (lane == 0) g_winner[b * (OH_ * OH_) + oh * OH_ + ow] = myk;
    }
}

// ---------------------------------------------------------------------------
// binning: hist / scan / block-aggregated scatter
// ---------------------------------------------------------------------------
__global__ void hist_kernel() {
    __shared__ int h[K_];
    const int tid = threadIdx.x;
    if (tid < K_) h[tid] = 0;
    __syncthreads();
    for (int i = blockIdx.x * blockDim.x + tid; i < LOCS; i += gridDim.x * blockDim.x)
        atomicAdd(&h[g_winner[i]], 1);
    __syncthreads();
    if (tid < K_ && h[tid]) atomicAdd(&g_counts[tid], h[tid]);
}

__global__ void scan_kernel() {
    __shared__ int s[K_];
    const int t = threadIdx.x;
    const int cnt = g_counts[t];
    s[t] = cnt;
    __syncthreads();
    for (int o = 1; o < K_; o <<= 1) {
        const int v = (t >= o) ? s[t - o] : 0;
        __syncthreads();
        s[t] += v;
        __syncthreads();
    }
    const int excl = s[t] - cnt;
    g_offs[t] = excl;
    g_cursor[t] = excl;
    if (t == K_ - 1) g_offs[K_] = s[K_ - 1];
}

// block-aggregated scatter: one global atomic per (block, k)
__global__ void scatter_kernel() {
    __shared__ int cnt[K_], base[K_], cur[K_];
    const int tid = threadIdx.x;
    const int per = (LOCS + gridDim.x - 1) / gridDim.x;
    const int s0 = blockIdx.x * per;
    int s1 = s0 + per; if (s1 > LOCS) s1 = LOCS;
    if (tid < K_) { cnt[tid] = 0; cur[tid] = 0; }
    __syncthreads();
    for (int idx = s0 + tid; idx < s1; idx += blockDim.x)
        atomicAdd(&cnt[g_winner[idx]], 1);
    __syncthreads();
    if (tid < K_)
        base[tid] = cnt[tid] ? atomicAdd(&g_cursor[tid], cnt[tid]) : 0;
    __syncthreads();
    for (int idx = s0 + tid; idx < s1; idx += blockDim.x) {
        const int k = g_winner[idx];
        const int off = atomicAdd(&cur[k], 1);
        const int b = idx / 3844, rem = idx % 3844;
        const int oh = rem / OH_, ow = rem % OH_;
        g_index[base[k] + off] = (b << 12) | (oh << 6) | ow;
    }
}

// ---------------------------------------------------------------------------
// hebb: NHWC gather, thread owns (tap, c-pair). grid (128 k, 4 chunks), 288 thr
// ---------------------------------------------------------------------------
__global__ void hebb_kernel(float* __restrict__ wu) {
    const int k = blockIdx.x, chunk = blockIdx.y;
    const int wid = threadIdx.x >> 5, lane = threadIdx.x & 31;
    const int i = wid / 3, j = wid % 3;
    const int start = g_offs[k], end = g_offs[k + 1];
    const int len = end - start;
    const int cs = start + (len * chunk) / 4;
    const int ce = start + (len * (chunk + 1)) / 4;
    float ax = 0.f, ay = 0.f;
    int p = cs;
    for (; p + 1 < ce; p += 2) {
        const int l0 = g_index[p], l1 = g_index[p + 1];
        const float2 v0 = *(const float2*)(g_xt +
            ((((l0 >> 12) * H_ + ((l0 >> 6) & 63) + i) * H_) + (l0 & 63) + j) * C_ + 2 * lane);
        const float2 v1 = *(const float2*)(g_xt +
            ((((l1 >> 12) * H_ + ((l1 >> 6) & 63) + i) * H_) + (l1 & 63) + j) * C_ + 2 * lane);
        ax += v0.x + v1.x; ay += v0.y + v1.y;
    }
    if (p < ce) {
        const int l0 = g_index[p];
        const float2 v0 = *(const float2*)(g_xt +
            ((((l0 >> 12) * H_ + ((l0 >> 6) & 63) + i) * H_) + (l0 & 63) + j) * C_ + 2 * lane);
        ax += v0.x; ay += v0.y;
    }
    const float sc = 1.f / 123008.f;
    atomicAdd(&wu[k * 576 + (2 * lane) * 9 + i * 3 + j], ax * sc);
    atomicAdd(&wu[k * 576 + (2 * lane + 1) * 9 + i * 3 + j], ay * sc);
}

// ---------------------------------------------------------------------------
extern "C" void kernel_launch(void* const* d_in, const int* in_sizes, int n_in,
                              void* d_out, int out_size) {
    const float* x    = (const float*)d_in[0];
    const float* w    = (const float*)d_in[1];
    const float* bias = (const float*)d_in[2];
    float* y  = (float*)d_out;
    float* wu = y + Y_ELEMS;

    cudaFuncSetAttribute(conv_mma_kernel,
                         cudaFuncAttributeMaxDynamicSharedMemorySize, SM_TOTAL);

    zero_kernel<<<72, 1024>>>(wu);
    transpose_kernel<<<dim3(64, 32), 256>>>(x);
    wnorm_kernel<<<K_, C_>>>(w);
    conv_mma_kernel<<<dim3(31, 32), 512, SM_TOTAL>>>(bias, y);
    fix_kernel<<<256, 128>>>(y, bias);
    hist_kernel<<<96, 256>>>();
    scan_kernel<<<1, K_>>>();
    scatter_kernel<<<96, 256>>>();
    hebb_kernel<<<dim3(K_, 4), 288>>>(wu);
}

// round 14
// speedup vs baseline: 2.2385x; 1.0728x over previous
#include <cuda_runtime.h>
#include <cuda_fp16.h>
#include <cstdint>

// Problem constants
#define B_   32
#define C_   64
#define K_   128
#define H_   64
#define OH_  62
#define LOCS 123008            // 32*62*62
#define Y_ELEMS 15745024       // 32*128*62*62
#define WU_ELEMS (K_ * C_ * 9)
#define MAXAMB 65536

// Static device scratch (no allocations allowed)
__device__ float g_xt[B_ * H_ * H_ * C_];   // x transposed to [b][h][w][c]
__device__ float g_wkt[K_ * C_ * 9];        // normalized weights [k][c][tap] fp32
__device__ uint4 g_wa[18 * 1152];           // 18 fp16 A slices [slice][k=128][72 fp16 padded]
__device__ int   g_winner[LOCS];
__device__ int   g_index[LOCS];
__device__ int   g_counts[K_];
__device__ int   g_offs[K_ + 1];
__device__ int   g_cursor[K_];
__device__ int   g_amb_cnt;
__device__ int   g_amb[MAXAMB];

// SMEM layout for conv (bytes) — xh tile, A pair-slice double-buffered
#define SM_BIAS 0
#define SM_XH   512
#define SM_A    (512 + 36864)                // 2 x 36864 (whi+wlo pair per buffer)
#define SM_YSM  (SM_A + 2 * 36864)
#define SM_TOTAL (SM_YSM + 128 * 132 * 4)    // 178688

__device__ __forceinline__ void mma_f16(float* d, const uint32_t* a,
                                        uint32_t b0, uint32_t b1) {
    asm volatile(
        "mma.sync.aligned.m16n8k16.row.col.f32.f16.f16.f32 "
        "{%0,%1,%2,%3}, {%4,%5,%6,%7}, {%8,%9}, {%0,%1,%2,%3};"
        : "+f"(d[0]), "+f"(d[1]), "+f"(d[2]), "+f"(d[3])
        : "r"(a[0]), "r"(a[1]), "r"(a[2]), "r"(a[3]), "r"(b0), "r"(b1));
}
__device__ __forceinline__ void ldsm_x4(uint32_t* r, uint32_t addr) {
    asm volatile("ldmatrix.sync.aligned.m8n8.x4.shared.b16 {%0,%1,%2,%3}, [%4];"
        : "=r"(r[0]), "=r"(r[1]), "=r"(r[2]), "=r"(r[3]) : "r"(addr));
}
__device__ __forceinline__ uint32_t smem_u32(const void* p) {
    return (uint32_t)__cvta_generic_to_shared(p);
}

// ---------------------------------------------------------------------------
// merged zero kernel
// ---------------------------------------------------------------------------
__global__ void zero_kernel(float* wu) {
    const int i = blockIdx.x * 1024 + threadIdx.x;
    if (i < WU_ELEMS) wu[i] = 0.f;
    if (blockIdx.x == 0) {
        if (threadIdx.x < K_) g_counts[threadIdx.x] = 0;
        if (threadIdx.x == 0) g_amb_cnt = 0;
    }
}

// ---------------------------------------------------------------------------
// transpose x -> [b][h][w][c]
// ---------------------------------------------------------------------------
__global__ void transpose_kernel(const float* __restrict__ x) {
    __shared__ float tile[64][65];
    const int h = blockIdx.x, b = blockIdx.y, tid = threadIdx.x;
    for (int idx = tid; idx < 4096; idx += 256) {
        const int c = idx >> 6, w = idx & 63;
        tile[c][w] = x[((b * C_ + c) * H_ + h) * H_ + w];
    }
    __syncthreads();
    for (int idx = tid; idx < 4096; idx += 256) {
        const int w = idx >> 6, c = idx & 63;
        g_xt[((b * H_ + h) * H_ + w) * C_ + c] = tile[c][w];
    }
}

// ---------------------------------------------------------------------------
// weight normalization -> g_wkt fp32 + 18 fp16 A slices (whi/wlo per tap)
// slice = j*6 + i*2 + var  (var 0 = whi, 1 = wlo)
// ---------------------------------------------------------------------------
__global__ void wnorm_kernel(const float* __restrict__ w) {
    const int k = blockIdx.x, c = threadIdx.x;
    const float* wp = w + (k * C_ + c) * 9;
    float v[9];
    float ssq = 0.f;
#pragma unroll
    for (int t = 0; t < 9; t++) { v[t] = wp[t]; ssq += v[t] * v[t]; }
#pragma unroll
    for (int o = 16; o; o >>= 1) ssq += __shfl_down_sync(0xffffffffu, ssq, o);
    __shared__ float red[2];
    if ((c & 31) == 0) red[c >> 5] = ssq;
    __syncthreads();
    const float total = red[0] + red[1];
    const float inv = (total == 0.f) ? 1.f : (1.f / sqrtf(total));
    unsigned short* wa = (unsigned short*)g_wa;
#pragma unroll
    for (int t = 0; t < 9; t++) {
        const float wn = v[t] * inv;
        g_wkt[k * 576 + c * 9 + t] = wn;
        const int i = t / 3, j = t % 3;
        __half hb = __float2half(wn);
        __half lb = __float2half(wn - __half2float(hb));
        const int s0 = j * 6 + i * 2;
        wa[(s0)     * 9216 + k * 72 + c] = *(unsigned short*)&hb;
        wa[(s0 + 1) * 9216 + k * 72 + c] = *(unsigned short*)&lb;
    }
}

// ---------------------------------------------------------------------------
// conv: mma.sync fp16 2-term split; 9 (j,i) iterations; B fragments loaded
// once per iteration and reused for both whi/wlo A passes; 9 syncs total.
// ---------------------------------------------------------------------------
__device__ __forceinline__ void dump_one(float* ysm, int row, int n, float v, int j) {
    const int w = n & 63;
    if (w >= j) {
        const int idx = row * 132 + n - j;
        if (j == 0) ysm[idx] = v;
        else        ysm[idx] += v;
    }
}

__global__ __launch_bounds__(512, 1)
void conv_mma_kernel(const float* __restrict__ bias,
                     float* __restrict__ y) {
    extern __shared__ char smem[];
    float*    biassm = (float*)(smem + SM_BIAS);
    float*    ysm = (float*)(smem + SM_YSM);

    const int tid = threadIdx.x;
    const int wid = tid >> 5, lane = tid & 31;
    const int g = lane >> 2, tig = lane & 3;
    const int lm = lane >> 3, lr = lane & 7;
    const int b = blockIdx.y;
    const int r = blockIdx.x * 2;
    const int mbase = (wid & 3) * 32;          // 4 m-groups
    const int nb = (wid >> 2) * 32;            // 4 n-groups

    const uint32_t sbase = smem_u32(smem);
    const uint32_t xh_base = sbase + SM_XH;
    const int A_lane_off = (mbase + (lm & 1) * 8 + lr) * 144 + (lm >> 1) * 16;
    const int B_lane_off = (nb + lr) * 144 + lm * 16;

    if (tid < K_) biassm[tid] = bias[tid];

    // convert x rows r..r+3 -> fp16 tile; 512 threads: (n', c-half)
    {
        unsigned short* xhu = (unsigned short*)(smem + SM_XH);
        const int np = tid & 255;               // n' row 0..255
        const int chalf = tid >> 8;             // 0 or 1 (32 c each)
        const int row = np >> 6, w = np & 63;
        const float4* xp = (const float4*)(g_xt +
            (((size_t)b * H_ + (r + row)) * H_ + w) * C_ + chalf * 32);
#pragma unroll
        for (int q = 0; q < 8; q++) {
            const float4 v4 = xp[q];
            const float vv[4] = {v4.x, v4.y, v4.z, v4.w};
#pragma unroll
            for (int u = 0; u < 4; u++) {
                const int c = chalf * 32 + q * 4 + u;
                __half hb = __float2half(vv[u]);
                xhu[np * 72 + c] = *(unsigned short*)&hb;
            }
        }
    }

    float acc[2][4][4];
#pragma unroll
    for (int mt = 0; mt < 2; mt++)
#pragma unroll
        for (int nt = 0; nt < 4; nt++)
#pragma unroll
            for (int q = 0; q < 4; q++) acc[mt][nt][q] = 0.f;

    // stage slice pair 0 (whi+wlo of tap (j=0,i=0)) into buf0
    {
        const uint4* gs = g_wa;
        uint4* d4 = (uint4*)(smem + SM_A);
#pragma unroll
        for (int q = 0; q < 5; q++) {
            const int idx = tid + 512 * q;
            if (idx < 2304) d4[idx] = gs[idx];
        }
    }
    __syncthreads();   // covers B tile + pair 0

    for (int s2 = 0; s2 < 9; s2++) {
        const uint32_t acur = sbase + SM_A + (uint32_t)(s2 & 1) * 36864;
        // stage next slice pair into the other buffer (LDG->STS overlaps compute;
        // g_wa is L2-resident, completes well before the end-of-iteration sync)
        if (s2 < 8) {
            const uint4* gs = g_wa + (size_t)(2 * (s2 + 1)) * 1152;
            uint4* d4 = (uint4*)(smem + SM_A + ((s2 + 1) & 1) * 36864);
#pragma unroll
            for (int q = 0; q < 5; q++) {
                const int idx = tid + 512 * q;
                if (idx < 2304) d4[idx] = gs[idx];
            }
        }
        const int j = s2 / 3, i = s2 % 3;

        // load B fragments ONCE for this (j,i); reuse for both A variants
        uint32_t Breg[2][4][4];
#pragma unroll
        for (int kh = 0; kh < 2; kh++)
#pragma unroll
            for (int nt = 0; nt < 4; nt++)
                ldsm_x4(Breg[kh][nt],
                        xh_base + B_lane_off + (i * 64 + nt * 8) * 144 + kh * 64);

#pragma unroll
        for (int var = 0; var < 2; var++) {
            const uint32_t abase = acur + (uint32_t)var * 18432;
#pragma unroll
            for (int kh = 0; kh < 2; kh++) {
                uint32_t Areg[2][2][4];
#pragma unroll
                for (int mt = 0; mt < 2; mt++)
#pragma unroll
                    for (int kl = 0; kl < 2; kl++)
                        ldsm_x4(Areg[mt][kl],
                                abase + A_lane_off + mt * 2304 + (kh * 2 + kl) * 32);
#pragma unroll
                for (int kl = 0; kl < 2; kl++)
#pragma unroll
                    for (int nt = 0; nt < 4; nt++) {
                        mma_f16(acc[0][nt], Areg[0][kl],
                                Breg[kh][nt][kl * 2], Breg[kh][nt][kl * 2 + 1]);
                        mma_f16(acc[1][nt], Areg[1][kl],
                                Breg[kh][nt][kl * 2], Breg[kh][nt][kl * 2 + 1]);
                    }
            }
        }

        if (i == 2) {  // end of j: dump D_j with column shift -j
#pragma unroll
            for (int mt = 0; mt < 2; mt++) {
                const int row0 = mbase + mt * 16 + g;
#pragma unroll
                for (int nt = 0; nt < 4; nt++) {
                    const int n0 = nb + nt * 8 + 2 * tig;
                    dump_one(ysm, row0,     n0,     acc[mt][nt][0], j);
                    dump_one(ysm, row0,     n0 + 1, acc[mt][nt][1], j);
                    dump_one(ysm, row0 + 8, n0,     acc[mt][nt][2], j);
                    dump_one(ysm, row0 + 8, n0 + 1, acc[mt][nt][3], j);
#pragma unroll
                    for (int q = 0; q < 4; q++) acc[mt][nt][q] = 0.f;
                }
            }
        }
        __syncthreads();   // pair boundary
    }

    // argmax + ambiguity flag (widened margin for fp16 2-term y error)
    if (tid < 124) {
        const int orow = (tid >= 62) ? 1 : 0;
        const int w = tid - orow * 62;
        const int n = orow * 64 + w;
        float best = -3.402823466e38f, second = -3.402823466e38f;
        int bk = 0;
#pragma unroll 4
        for (int k = 0; k < K_; k++) {
            const float v = ysm[k * 132 + n] + biassm[k];
            if (v > best) { second = best; best = v; bk = k; }
            else if (v > second) second = v;
        }
        const int oh = r + orow;
        g_winner[b * (OH_ * OH_) + oh * OH_ + w] = bk;
        if (best - second < 2.5e-3f) {
            const int p = atomicAdd(&g_amb_cnt, 1);
            if (p < MAXAMB) g_amb[p] = (b << 12) | (oh << 6) | w;
        }
    }

    // coalesced y store: 16 warps x 16 (k,orow) rows
    {
#pragma unroll 4
        for (int rr = 0; rr < 16; rr++) {
            const int rowid = wid * 16 + rr;
            const int k = rowid >> 1, orow = rowid & 1;
            const float bk = biassm[k];
            float* ydst = y + (((size_t)b * K_ + k) * OH_ + (r + orow)) * OH_;
            const float* ysrc = ysm + k * 132 + orow * 64;
#pragma unroll
            for (int hh = 0; hh < 2; hh++) {
                const int w = hh * 32 + lane;
                if (w < OH_) ydst[w] = ysrc[w] + bk;
            }
        }
    }
}

// ---------------------------------------------------------------------------
// exact fp32 winner recompute for ambiguous locations (order matches the
// empirically-reference-matching round-2 scalar chain).
// ---------------------------------------------------------------------------
__global__ void fix_kernel(const float* __restrict__ y,
                           const float* __restrict__ bias) {
    int cnt = g_amb_cnt; if (cnt > MAXAMB) cnt = MAXAMB;
    const int gw = (blockIdx.x * blockDim.x + threadIdx.x) >> 5;
    const int lane = threadIdx.x & 31;
    const int nw = (gridDim.x * blockDim.x) >> 5;
    for (int e = gw; e < cnt; e += nw) {
        const int loc = g_amb[e];
        const int b = loc >> 12, oh = (loc >> 6) & 63, ow = loc & 63;
        float v[4];
#pragma unroll
        for (int q = 0; q < 4; q++)
            v[q] = y[((size_t)(b * K_ + q * 32 + lane) * OH_ + oh) * OH_ + ow];
        float m = fmaxf(fmaxf(v[0], v[1]), fmaxf(v[2], v[3]));
#pragma unroll
        for (int o = 16; o; o >>= 1) m = fmaxf(m, __shfl_xor_sync(0xffffffffu, m, o));

        float myval = -3.402823466e38f;
        int   myk   = 0x7fffffff;
        int cidx = 0;
#pragma unroll
        for (int q = 0; q < 4; q++) {
            unsigned mask = __ballot_sync(0xffffffffu, v[q] >= m - 2.5e-3f);
            while (mask) {
                const int src = __ffs(mask) - 1;
                mask &= mask - 1;
                const int k = q * 32 + src;
                if ((cidx & 31) == lane) {
                    const float* wk = g_wkt + k * 576;
                    const float* xb = g_xt + (((size_t)b * H_ + oh) * H_ + ow) * C_;
                    float s = 0.f;
                    for (int c = 0; c < C_; c++) {
                        const float* wc = wk + c * 9;
#pragma unroll
                        for (int i = 0; i < 3; i++) {
#pragma unroll
                            for (int j = 0; j < 3; j++)
                                s = fmaf(wc[i * 3 + j],
                                         xb[(i * H_ + j) * C_ + c], s);
                        }
                    }
                    const float val = s + bias[k];
                    if (val > myval || (val == myval && k < myk)) {
                        myval = val; myk = k;
                    }
                }
                cidx++;
            }
        }
#pragma unroll
        for (int o = 16; o; o >>= 1) {
            const float ov = __shfl_xor_sync(0xffffffffu, myval, o);
            const int   ok = __shfl_xor_sync(0xffffffffu, myk, o);
            if (ov > myval || (ov == myval && ok < myk)) { myval = ov; myk = ok; }
        }
        if (lane == 0) g_winner[b * (OH_ * OH_) + oh * OH_ + ow] = myk;
    }
}

// ---------------------------------------------------------------------------
// binning: hist / scan / block-aggregated scatter
// ---------------------------------------------------------------------------
__global__ void hist_kernel() {
    __shared__ int h[K_];
    const int tid = threadIdx.x;
    if (tid < K_) h[tid] = 0;
    __syncthreads();
    for (int i = blockIdx.x * blockDim.x + tid; i < LOCS; i += gridDim.x * blockDim.x)
        atomicAdd(&h[g_winner[i]], 1);
    __syncthreads();
    if (tid < K_ && h[tid]) atomicAdd(&g_counts[tid], h[tid]);
}

__global__ void scan_kernel() {
    __shared__ int s[K_];
    const int t = threadIdx.x;
    const int cnt = g_counts[t];
    s[t] = cnt;
    __syncthreads();
    for (int o = 1; o < K_; o <<= 1) {
        const int v = (t >= o) ? s[t - o] : 0;
        __syncthreads();
        s[t] += v;
        __syncthreads();
    }
    const int excl = s[t] - cnt;
    g_offs[t] = excl;
    g_cursor[t] = excl;
    if (t == K_ - 1) g_offs[K_] = s[K_ - 1];
}

// block-aggregated scatter: one global atomic per (block, k)
__global__ void scatter_kernel() {
    __shared__ int cnt[K_], base[K_], cur[K_];
    const int tid = threadIdx.x;
    const int per = (LOCS + gridDim.x - 1) / gridDim.x;
    const int s0 = blockIdx.x * per;
    int s1 = s0 + per; if (s1 > LOCS) s1 = LOCS;
    if (tid < K_) { cnt[tid] = 0; cur[tid] = 0; }
    __syncthreads();
    for (int idx = s0 + tid; idx < s1; idx += blockDim.x)
        atomicAdd(&cnt[g_winner[idx]], 1);
    __syncthreads();
    if (tid < K_)
        base[tid] = cnt[tid] ? atomicAdd(&g_cursor[tid], cnt[tid]) : 0;
    __syncthreads();
    for (int idx = s0 + tid; idx < s1; idx += blockDim.x) {
        const int k = g_winner[idx];
        const int off = atomicAdd(&cur[k], 1);
        const int b = idx / 3844, rem = idx % 3844;
        const int oh = rem / OH_, ow = rem % OH_;
        g_index[base[k] + off] = (b << 12) | (oh << 6) | ow;
    }
}

// ---------------------------------------------------------------------------
// hebb: NHWC gather, thread owns (tap, c-pair). grid (128 k, 4 chunks), 288 thr
// ---------------------------------------------------------------------------
__global__ void hebb_kernel(float* __restrict__ wu) {
    const int k = blockIdx.x, chunk = blockIdx.y;
    const int wid = threadIdx.x >> 5, lane = threadIdx.x & 31;
    const int i = wid / 3, j = wid % 3;
    const int start = g_offs[k], end = g_offs[k + 1];
    const int len = end - start;
    const int cs = start + (len * chunk) / 4;
    const int ce = start + (len * (chunk + 1)) / 4;
    float ax = 0.f, ay = 0.f;
    int p = cs;
    for (; p + 1 < ce; p += 2) {
        const int l0 = g_index[p], l1 = g_index[p + 1];
        const float2 v0 = *(const float2*)(g_xt +
            ((((l0 >> 12) * H_ + ((l0 >> 6) & 63) + i) * H_) + (l0 & 63) + j) * C_ + 2 * lane);
        const float2 v1 = *(const float2*)(g_xt +
            ((((l1 >> 12) * H_ + ((l1 >> 6) & 63) + i) * H_) + (l1 & 63) + j) * C_ + 2 * lane);
        ax += v0.x + v1.x; ay += v0.y + v1.y;
    }
    if (p < ce) {
        const int l0 = g_index[p];
        const float2 v0 = *(const float2*)(g_xt +
            ((((l0 >> 12) * H_ + ((l0 >> 6) & 63) + i) * H_) + (l0 & 63) + j) * C_ + 2 * lane);
        ax += v0.x; ay += v0.y;
    }
    const float sc = 1.f / 123008.f;
    atomicAdd(&wu[k * 576 + (2 * lane) * 9 + i * 3 + j], ax * sc);
    atomicAdd(&wu[k * 576 + (2 * lane + 1) * 9 + i * 3 + j], ay * sc);
}

// ---------------------------------------------------------------------------
extern "C" void kernel_launch(void* const* d_in, const int* in_sizes, int n_in,
                              void* d_out, int out_size) {
    const float* x    = (const float*)d_in[0];
    const float* w    = (const float*)d_in[1];
    const float* bias = (const float*)d_in[2];
    float* y  = (float*)d_out;
    float* wu = y + Y_ELEMS;

    cudaFuncSetAttribute(conv_mma_kernel,
                         cudaFuncAttributeMaxDynamicSharedMemorySize, SM_TOTAL);

    zero_kernel<<<72, 1024>>>(wu);
    transpose_kernel<<<dim3(64, 32), 256>>>(x);
    wnorm_kernel<<<K_, C_>>>(w);
    conv_mma_kernel<<<dim3(31, 32), 512, SM_TOTAL>>>(bias, y);
    fix_kernel<<<256, 128>>>(y, bias);
    hist_kernel<<<96, 256>>>();
    scan_kernel<<<1, K_>>>();
    scatter_kernel<<<96, 256>>>();
    hebb_kernel<<<dim3(K_, 4), 288>>>(wu);
}

// round 15
// speedup vs baseline: 2.6111x; 1.1664x over previous
#include <cuda_runtime.h>
#include <cuda_fp16.h>
#include <cstdint>

// Problem constants
#define B_   32
#define C_   64
#define K_   128
#define H_   64
#define OH_  62
#define LOCS 123008            // 32*62*62
#define Y_ELEMS 15745024       // 32*128*62*62
#define WU_ELEMS (K_ * C_ * 9)
#define MAXAMB 65536

// Static device scratch (no allocations allowed)
__device__ float g_xt[B_ * H_ * H_ * C_];   // x transposed to [b][h][w][c]
__device__ float g_wkt[K_ * C_ * 9];        // normalized weights [k][c][tap] fp32
__device__ uint4 g_wa[9 * 1152];            // 9 fp16 A slices [tap][k=128][72 fp16 padded]
__device__ int   g_winner[LOCS];
__device__ int   g_index[LOCS];
__device__ int   g_counts[K_];
__device__ int   g_offs[K_ + 1];
__device__ int   g_cursor[K_];
__device__ int   g_amb_cnt;
__device__ int   g_amb[MAXAMB];

// SMEM layout for conv (bytes) — xh tile, A single-slice double-buffered
#define SM_BIAS 0
#define SM_XH   512
#define SM_A    (512 + 36864)                // 2 x 18432
#define SM_YSM  (SM_A + 2 * 18432)
#define SM_TOTAL (SM_YSM + 128 * 132 * 4)    // 141824

#define AMB_MARGIN 5e-3f

__device__ __forceinline__ void mma_f16(float* d, const uint32_t* a,
                                        uint32_t b0, uint32_t b1) {
    asm volatile(
        "mma.sync.aligned.m16n8k16.row.col.f32.f16.f16.f32 "
        "{%0,%1,%2,%3}, {%4,%5,%6,%7}, {%8,%9}, {%0,%1,%2,%3};"
        : "+f"(d[0]), "+f"(d[1]), "+f"(d[2]), "+f"(d[3])
        : "r"(a[0]), "r"(a[1]), "r"(a[2]), "r"(a[3]), "r"(b0), "r"(b1));
}
__device__ __forceinline__ void ldsm_x4(uint32_t* r, uint32_t addr) {
    asm volatile("ldmatrix.sync.aligned.m8n8.x4.shared.b16 {%0,%1,%2,%3}, [%4];"
        : "=r"(r[0]), "=r"(r[1]), "=r"(r[2]), "=r"(r[3]) : "r"(addr));
}
__device__ __forceinline__ uint32_t smem_u32(const void* p) {
    return (uint32_t)__cvta_generic_to_shared(p);
}

// ---------------------------------------------------------------------------
// merged zero kernel
// ---------------------------------------------------------------------------
__global__ void zero_kernel(float* wu) {
    const int i = blockIdx.x * 1024 + threadIdx.x;
    if (i < WU_ELEMS) wu[i] = 0.f;
    if (blockIdx.x == 0) {
        if (threadIdx.x < K_) g_counts[threadIdx.x] = 0;
        if (threadIdx.x == 0) g_amb_cnt = 0;
    }
}

// ---------------------------------------------------------------------------
// transpose x -> [b][h][w][c]
// ---------------------------------------------------------------------------
__global__ void transpose_kernel(const float* __restrict__ x) {
    __shared__ float tile[64][65];
    const int h = blockIdx.x, b = blockIdx.y, tid = threadIdx.x;
    for (int idx = tid; idx < 4096; idx += 256) {
        const int c = idx >> 6, w = idx & 63;
        tile[c][w] = x[((b * C_ + c) * H_ + h) * H_ + w];
    }
    __syncthreads();
    for (int idx = tid; idx < 4096; idx += 256) {
        const int w = idx >> 6, c = idx & 63;
        g_xt[((b * H_ + h) * H_ + w) * C_ + c] = tile[c][w];
    }
}

// ---------------------------------------------------------------------------
// weight normalization -> g_wkt fp32 + 9 fp16 A slices (one per tap)
// slice = j*3 + i
// ---------------------------------------------------------------------------
__global__ void wnorm_kernel(const float* __restrict__ w) {
    const int k = blockIdx.x, c = threadIdx.x;
    const float* wp = w + (k * C_ + c) * 9;
    float v[9];
    float ssq = 0.f;
#pragma unroll
    for (int t = 0; t < 9; t++) { v[t] = wp[t]; ssq += v[t] * v[t]; }
#pragma unroll
    for (int o = 16; o; o >>= 1) ssq += __shfl_down_sync(0xffffffffu, ssq, o);
    __shared__ float red[2];
    if ((c & 31) == 0) red[c >> 5] = ssq;
    __syncthreads();
    const float total = red[0] + red[1];
    const float inv = (total == 0.f) ? 1.f : (1.f / sqrtf(total));
    unsigned short* wa = (unsigned short*)g_wa;
#pragma unroll
    for (int t = 0; t < 9; t++) {
        const float wn = v[t] * inv;
        g_wkt[k * 576 + c * 9 + t] = wn;
        const int i = t / 3, j = t % 3;
        __half hb = __float2half(wn);
        wa[(j * 3 + i) * 9216 + k * 72 + c] = *(unsigned short*)&hb;
    }
}

// ---------------------------------------------------------------------------
// conv: mma.sync fp16 single-term; 9 (j,i) iterations, B fragments loaded
// once per iteration; hist fused into the argmax epilogue.
// ---------------------------------------------------------------------------
__device__ __forceinline__ void dump_one(float* ysm, int row, int n, float v, int j) {
    const int w = n & 63;
    if (w >= j) {
        const int idx = row * 132 + n - j;
        if (j == 0) ysm[idx] = v;
        else        ysm[idx] += v;
    }
}

__global__ __launch_bounds__(512, 1)
void conv_mma_kernel(const float* __restrict__ bias,
                     float* __restrict__ y) {
    extern __shared__ char smem[];
    float*    biassm = (float*)(smem + SM_BIAS);
    float*    ysm = (float*)(smem + SM_YSM);

    const int tid = threadIdx.x;
    const int wid = tid >> 5, lane = tid & 31;
    const int g = lane >> 2, tig = lane & 3;
    const int lm = lane >> 3, lr = lane & 7;
    const int b = blockIdx.y;
    const int r = blockIdx.x * 2;
    const int mbase = (wid & 3) * 32;          // 4 m-groups
    const int nb = (wid >> 2) * 32;            // 4 n-groups

    const uint32_t sbase = smem_u32(smem);
    const uint32_t xh_base = sbase + SM_XH;
    const int A_lane_off = (mbase + (lm & 1) * 8 + lr) * 144 + (lm >> 1) * 16;
    const int B_lane_off = (nb + lr) * 144 + lm * 16;

    if (tid < K_) biassm[tid] = bias[tid];

    // convert x rows r..r+3 -> fp16 tile; 512 threads: (n', c-half)
    {
        unsigned short* xhu = (unsigned short*)(smem + SM_XH);
        const int np = tid & 255;               // n' row 0..255
        const int chalf = tid >> 8;             // 0 or 1 (32 c each)
        const int row = np >> 6, w = np & 63;
        const float4* xp = (const float4*)(g_xt +
            (((size_t)b * H_ + (r + row)) * H_ + w) * C_ + chalf * 32);
#pragma unroll
        for (int q = 0; q < 8; q++) {
            const float4 v4 = xp[q];
            const float vv[4] = {v4.x, v4.y, v4.z, v4.w};
#pragma unroll
            for (int u = 0; u < 4; u++) {
                const int c = chalf * 32 + q * 4 + u;
                __half hb = __float2half(vv[u]);
                xhu[np * 72 + c] = *(unsigned short*)&hb;
            }
        }
    }

    float acc[2][4][4];
#pragma unroll
    for (int mt = 0; mt < 2; mt++)
#pragma unroll
        for (int nt = 0; nt < 4; nt++)
#pragma unroll
            for (int q = 0; q < 4; q++) acc[mt][nt][q] = 0.f;

    // stage slice 0 into buf0
    {
        const uint4* gs = g_wa;
        uint4* d4 = (uint4*)(smem + SM_A);
#pragma unroll
        for (int q = 0; q < 3; q++) {
            const int idx = tid + 512 * q;
            if (idx < 1152) d4[idx] = gs[idx];
        }
    }
    __syncthreads();   // covers B tile + slice 0

    for (int s2 = 0; s2 < 9; s2++) {
        const uint32_t acur = sbase + SM_A + (uint32_t)(s2 & 1) * 18432;
        // stage next slice into the other buffer (LDG->STS overlaps compute)
        if (s2 < 8) {
            const uint4* gs = g_wa + (size_t)(s2 + 1) * 1152;
            uint4* d4 = (uint4*)(smem + SM_A + ((s2 + 1) & 1) * 18432);
#pragma unroll
            for (int q = 0; q < 3; q++) {
                const int idx = tid + 512 * q;
                if (idx < 1152) d4[idx] = gs[idx];
            }
        }
        const int j = s2 / 3, i = s2 % 3;

        // B fragments once per (j,i)
        uint32_t Breg[2][4][4];
#pragma unroll
        for (int kh = 0; kh < 2; kh++)
#pragma unroll
            for (int nt = 0; nt < 4; nt++)
                ldsm_x4(Breg[kh][nt],
                        xh_base + B_lane_off + (i * 64 + nt * 8) * 144 + kh * 64);

#pragma unroll
        for (int kh = 0; kh < 2; kh++) {
            uint32_t Areg[2][2][4];
#pragma unroll
            for (int mt = 0; mt < 2; mt++)
#pragma unroll
                for (int kl = 0; kl < 2; kl++)
                    ldsm_x4(Areg[mt][kl],
                            acur + A_lane_off + mt * 2304 + (kh * 2 + kl) * 32);
#pragma unroll
            for (int kl = 0; kl < 2; kl++)
#pragma unroll
                for (int nt = 0; nt < 4; nt++) {
                    mma_f16(acc[0][nt], Areg[0][kl],
                            Breg[kh][nt][kl * 2], Breg[kh][nt][kl * 2 + 1]);
                    mma_f16(acc[1][nt], Areg[1][kl],
                            Breg[kh][nt][kl * 2], Breg[kh][nt][kl * 2 + 1]);
                }
        }

        if (i == 2) {  // end of j: dump D_j with column shift -j
#pragma unroll
            for (int mt = 0; mt < 2; mt++) {
                const int row0 = mbase + mt * 16 + g;
#pragma unroll
                for (int nt = 0; nt < 4; nt++) {
                    const int n0 = nb + nt * 8 + 2 * tig;
                    dump_one(ysm, row0,     n0,     acc[mt][nt][0], j);
                    dump_one(ysm, row0,     n0 + 1, acc[mt][nt][1], j);
                    dump_one(ysm, row0 + 8, n0,     acc[mt][nt][2], j);
                    dump_one(ysm, row0 + 8, n0 + 1, acc[mt][nt][3], j);
#pragma unroll
                    for (int q = 0; q < 4; q++) acc[mt][nt][q] = 0.f;
                }
            }
        }
        __syncthreads();   // slice boundary
    }

    // argmax + fused hist + ambiguity flag
    if (tid < 124) {
        const int orow = (tid >= 62) ? 1 : 0;
        const int w = tid - orow * 62;
        const int n = orow * 64 + w;
        float best = -3.402823466e38f, second = -3.402823466e38f;
        int bk = 0;
#pragma unroll 4
        for (int k = 0; k < K_; k++) {
            const float v = ysm[k * 132 + n] + biassm[k];
            if (v > best) { second = best; best = v; bk = k; }
            else if (v > second) second = v;
        }
        const int oh = r + orow;
        g_winner[b * (OH_ * OH_) + oh * OH_ + w] = bk;
        atomicAdd(&g_counts[bk], 1);
        if (best - second < AMB_MARGIN) {
            const int p = atomicAdd(&g_amb_cnt, 1);
            if (p < MAXAMB) g_amb[p] = (b << 12) | (oh << 6) | w;
        }
    }

    // coalesced y store: 16 warps x 16 (k,orow) rows
    {
#pragma unroll 4
        for (int rr = 0; rr < 16; rr++) {
            const int rowid = wid * 16 + rr;
            const int k = rowid >> 1, orow = rowid & 1;
            const float bk = biassm[k];
            float* ydst = y + (((size_t)b * K_ + k) * OH_ + (r + orow)) * OH_;
            const float* ysrc = ysm + k * 132 + orow * 64;
#pragma unroll
            for (int hh = 0; hh < 2; hh++) {
                const int w = hh * 32 + lane;
                if (w < OH_) ydst[w] = ysrc[w] + bk;
            }
        }
    }
}

// ---------------------------------------------------------------------------
// exact fp32 winner recompute for ambiguous locations (order matches the
// empirically-reference-matching round-2 scalar chain). Adjusts fused hist
// counts when it flips a winner.
// ---------------------------------------------------------------------------
__global__ void fix_kernel(const float* __restrict__ y,
                           const float* __restrict__ bias) {
    int cnt = g_amb_cnt; if (cnt > MAXAMB) cnt = MAXAMB;
    const int gw = (blockIdx.x * blockDim.x + threadIdx.x) >> 5;
    const int lane = threadIdx.x & 31;
    const int nw = (gridDim.x * blockDim.x) >> 5;
    for (int e = gw; e < cnt; e += nw) {
        const int loc = g_amb[e];
        const int b = loc >> 12, oh = (loc >> 6) & 63, ow = loc & 63;
        float v[4];
#pragma unroll
        for (int q = 0; q < 4; q++)
            v[q] = y[((size_t)(b * K_ + q * 32 + lane) * OH_ + oh) * OH_ + ow];
        float m = fmaxf(fmaxf(v[0], v[1]), fmaxf(v[2], v[3]));
#pragma unroll
        for (int o = 16; o; o >>= 1) m = fmaxf(m, __shfl_xor_sync(0xffffffffu, m, o));

        float myval = -3.402823466e38f;
        int   myk   = 0x7fffffff;
        int cidx = 0;
#pragma unroll
        for (int q = 0; q < 4; q++) {
            unsigned mask = __ballot_sync(0xffffffffu, v[q] >= m - AMB_MARGIN);
            while (mask) {
                const int src = __ffs(mask) - 1;
                mask &= mask - 1;
                const int k = q * 32 + src;
                if ((cidx & 31) == lane) {
                    const float* wk = g_wkt + k * 576;
                    const float* xb = g_xt + (((size_t)b * H_ + oh) * H_ + ow) * C_;
                    float s = 0.f;
                    for (int c = 0; c < C_; c++) {
                        const float* wc = wk + c * 9;
#pragma unroll
                        for (int i = 0; i < 3; i++) {
#pragma unroll
                            for (int j = 0; j < 3; j++)
                                s = fmaf(wc[i * 3 + j],
                                         xb[(i * H_ + j) * C_ + c], s);
                        }
                    }
                    const float val = s + bias[k];
                    if (val > myval || (val == myval && k < myk)) {
                        myval = val; myk = k;
                    }
                }
                cidx++;
            }
        }
#pragma unroll
        for (int o = 16; o; o >>= 1) {
            const float ov = __shfl_xor_sync(0xffffffffu, myval, o);
            const int   ok = __shfl_xor_sync(0xffffffffu, myk, o);
            if (ov > myval || (ov == myval && ok < myk)) { myval = ov; myk = ok; }
        }
        if (lane == 0) {
            const int idx = b * (OH_ * OH_) + oh * OH_ + ow;
            const int old = g_winner[idx];
            if (myk != old) {
                g_winner[idx] = myk;
                atomicAdd(&g_counts[myk], 1);
                atomicSub(&g_counts[old], 1);
            }
        }
    }
}

// ---------------------------------------------------------------------------
// binning: scan / block-aggregated scatter (hist now fused into conv)
// ---------------------------------------------------------------------------
__global__ void scan_kernel() {
    __shared__ int s[K_];
    const int t = threadIdx.x;
    const int cnt = g_counts[t];
    s[t] = cnt;
    __syncthreads();
    for (int o = 1; o < K_; o <<= 1) {
        const int v = (t >= o) ? s[t - o] : 0;
        __syncthreads();
        s[t] += v;
        __syncthreads();
    }
    const int excl = s[t] - cnt;
    g_offs[t] = excl;
    g_cursor[t] = excl;
    if (t == K_ - 1) g_offs[K_] = s[K_ - 1];
}

// block-aggregated scatter: one global atomic per (block, k)
__global__ void scatter_kernel() {
    __shared__ int cnt[K_], base[K_], cur[K_];
    const int tid = threadIdx.x;
    const int per = (LOCS + gridDim.x - 1) / gridDim.x;
    const int s0 = blockIdx.x * per;
    int s1 = s0 + per; if (s1 > LOCS) s1 = LOCS;
    if (tid < K_) { cnt[tid] = 0; cur[tid] = 0; }
    __syncthreads();
    for (int idx = s0 + tid; idx < s1; idx += blockDim.x)
        atomicAdd(&cnt[g_winner[idx]], 1);
    __syncthreads();
    if (tid < K_)
        base[tid] = cnt[tid] ? atomicAdd(&g_cursor[tid], cnt[tid]) : 0;
    __syncthreads();
    for (int idx = s0 + tid; idx < s1; idx += blockDim.x) {
        const int k = g_winner[idx];
        const int off = atomicAdd(&cur[k], 1);
        const int b = idx / 3844, rem = idx % 3844;
        const int oh = rem / OH_, ow = rem % OH_;
        g_index[base[k] + off] = (b << 12) | (oh << 6) | ow;
    }
}

// ---------------------------------------------------------------------------
// hebb: NHWC gather, thread owns (tap, c-pair). grid (128 k, 4 chunks), 288 thr
// ---------------------------------------------------------------------------
__global__ void hebb_kernel(float* __restrict__ wu) {
    const int k = blockIdx.x, chunk = blockIdx.y;
    const int wid = threadIdx.x >> 5, lane = threadIdx.x & 31;
    const int i = wid / 3, j = wid % 3;
    const int start = g_offs[k], end = g_offs[k + 1];
    const int len = end - start;
    const int cs = start + (len * chunk) / 4;
    const int ce = start + (len * (chunk + 1)) / 4;
    float ax = 0.f, ay = 0.f;
    int p = cs;
    for (; p + 1 < ce; p += 2) {
        const int l0 = g_index[p], l1 = g_index[p + 1];
        const float2 v0 = *(const float2*)(g_xt +
            ((((l0 >> 12) * H_ + ((l0 >> 6) & 63) + i) * H_) + (l0 & 63) + j) * C_ + 2 * lane);
        const float2 v1 = *(const float2*)(g_xt +
            ((((l1 >> 12) * H_ + ((l1 >> 6) & 63) + i) * H_) + (l1 & 63) + j) * C_ + 2 * lane);
        ax += v0.x + v1.x; ay += v0.y + v1.y;
    }
    if (p < ce) {
        const int l0 = g_index[p];
        const float2 v0 = *(const float2*)(g_xt +
            ((((l0 >> 12) * H_ + ((l0 >> 6) & 63) + i) * H_) + (l0 & 63) + j) * C_ + 2 * lane);
        ax += v0.x; ay += v0.y;
    }
    const float sc = 1.f / 123008.f;
    atomicAdd(&wu[k * 576 + (2 * lane) * 9 + i * 3 + j], ax * sc);
    atomicAdd(&wu[k * 576 + (2 * lane + 1) * 9 + i * 3 + j], ay * sc);
}

// ---------------------------------------------------------------------------
extern "C" void kernel_launch(void* const* d_in, const int* in_sizes, int n_in,
                              void* d_out, int out_size) {
    const float* x    = (const float*)d_in[0];
    const float* w    = (const float*)d_in[1];
    const float* bias = (const float*)d_in[2];
    float* y  = (float*)d_out;
    float* wu = y + Y_ELEMS;

    cudaFuncSetAttribute(conv_mma_kernel,
                         cudaFuncAttributeMaxDynamicSharedMemorySize, SM_TOTAL);

    zero_kernel<<<72, 1024>>>(wu);
    transpose_kernel<<<dim3(64, 32), 256>>>(x);
    wnorm_kernel<<<K_, C_>>>(w);
    conv_mma_kernel<<<dim3(31, 32), 512, SM_TOTAL>>>(bias, y);
    fix_kernel<<<512, 256>>>(y, bias);
    scan_kernel<<<1, K_>>>();
    scatter_kernel<<<96, 256>>>();
    hebb_kernel<<<dim3(K_, 4), 288>>>(wu);
}